// round 14
// baseline (speedup 1.0000x reference)
#include <cuda_runtime.h>
#include <cuda_bf16.h>
#include <math.h>
#include <stdint.h>

#define BATCH 2
#define SEQ   2048
#define DM    1024
#define NH    16
#define HD    64
#define UTOP  38
#define QB    8
#define NELM  (BATCH*SEQ*DM)   // 4194304

// ---------------------------------------------------------------------------
// Scratch (allocation-free rule: __device__ globals)
// ---------------------------------------------------------------------------
__device__ float g_S[(size_t)BATCH*NH*SEQ*SEQ];   // 536 MB score matrix
__device__ float g_V[BATCH*NH*SEQ*HD];            // V, head-major fp32
__device__ __nv_bfloat16 g_xh[NELM],  g_xl[NELM];
__device__ __nv_bfloat16 g_Wvh[DM*DM], g_Wvl[DM*DM];
__device__ __nv_bfloat16 g_Woh[DM*DM], g_Wol[DM*DM];
__device__ __nv_bfloat16 g_Qh[NELM], g_Qm[NELM], g_Ql[NELM];   // head-major
__device__ __nv_bfloat16 g_Kh[NELM], g_Km[NELM], g_Kl[NELM];   // head-major
__device__ __nv_bfloat16 g_Ch[NELM], g_Cl[NELM];               // context hi/lo

// ---------------------------------------------------------------------------
// helpers
// ---------------------------------------------------------------------------
__device__ __forceinline__ unsigned f2u(float f) {
    unsigned u = __float_as_uint(f);
    return (u & 0x80000000u) ? ~u : (u | 0x80000000u);
}
__device__ __forceinline__ float u2f(unsigned m) {
    return __uint_as_float((m & 0x80000000u) ? (m & 0x7FFFFFFFu) : ~m);
}
__device__ __forceinline__ size_t hm_dest(int m, int n) {
    int b = m >> 11, q = m & (SEQ-1);
    int h = n >> 6,  d = n & (HD-1);
    return ((size_t)b << 21) + ((size_t)h << 17) + ((size_t)q << 6) + d;
}
__device__ __forceinline__ uint32_t smem_to_u32(const void* p) {
    uint32_t a;
    asm("{ .reg .u64 tmp; cvta.to.shared.u64 tmp, %1; cvt.u32.u64 %0, tmp; }"
        : "=r"(a) : "l"(p));
    return a;
}

// m16n8k16 bf16 MMA, fp32 accumulate (arch-neutral PTX -> HMMA)
__device__ __forceinline__ void mma16816(float c[4], const uint32_t a[4],
                                         const uint32_t b[2]) {
    asm volatile(
        "mma.sync.aligned.m16n8k16.row.col.f32.bf16.bf16.f32 "
        "{%0,%1,%2,%3}, {%4,%5,%6,%7}, {%8,%9}, {%0,%1,%2,%3};"
        : "+f"(c[0]), "+f"(c[1]), "+f"(c[2]), "+f"(c[3])
        : "r"(a[0]), "r"(a[1]), "r"(a[2]), "r"(a[3]), "r"(b[0]), "r"(b[1]));
}
// ldmatrix x4 (arch-neutral, sm_75+)
__device__ __forceinline__ void ldm_x4(uint32_t r[4], uint32_t addr) {
    asm volatile("ldmatrix.sync.aligned.m8n8.x4.shared.b16 {%0,%1,%2,%3}, [%4];"
        : "=r"(r[0]), "=r"(r[1]), "=r"(r[2]), "=r"(r[3]) : "r"(addr));
}

// ---------------------------------------------------------------------------
// bf16 split kernel
// ---------------------------------------------------------------------------
__global__ void split2_kernel(const float* __restrict__ in,
                              __nv_bfloat16* __restrict__ hi,
                              __nv_bfloat16* __restrict__ lo, int n)
{
    int i = blockIdx.x * blockDim.x + threadIdx.x;
    if (i < n) {
        float v = in[i];
        __nv_bfloat16 h = __float2bfloat16(v);
        hi[i] = h;
        lo[i] = __float2bfloat16(v - __bfloat162float(h));
    }
}

// ---------------------------------------------------------------------------
// Tensor GEMM via mma.sync + ldmatrix. C[M,N] = alpha*sum_pairs(Ai@Bj^T)+bias
// Block tile 128x128, 8 warps (4m x 2n), warp tile 32x64, K chunks of 64.
// smem pitch 36 u32 (conflict-free ldmatrix). Pair ORDER preserved exactly
// (bitwise-identical S to round 10/11); A fragments for all planes are
// hoisted per k16-step and reused across pairs (LDSM 36->30 / 18->16).
// ---------------------------------------------------------------------------
#define PITCH 36
#define PLANE (128*PITCH)   // u32 per plane

template<int NSPLIT>
__global__ __launch_bounds__(256, 2) void gemm_mma(
    const __nv_bfloat16* __restrict__ A0, const __nv_bfloat16* __restrict__ A1,
    const __nv_bfloat16* __restrict__ A2, int lda, size_t sA,
    const __nv_bfloat16* __restrict__ B0, const __nv_bfloat16* __restrict__ B1,
    const __nv_bfloat16* __restrict__ B2, int ldb, size_t sB,
    const float* __restrict__ bias,
    float* __restrict__ Cout, int ldc, size_t sC,
    int Kdim, float alpha, int headmajor)
{
    extern __shared__ uint32_t sm[];
    uint32_t* Asm = sm;                    // [NSPLIT][PLANE]
    uint32_t* Bsm = sm + NSPLIT*PLANE;     // [NSPLIT][PLANE]
    const uint32_t sbase = smem_to_u32(sm);

    const int t    = threadIdx.x;
    const int wid  = t >> 5, lane = t & 31;
    const int wm   = wid & 3, wn = wid >> 2;
    const int g    = lane >> 2;
    const int tq   = lane & 3;
    const int m0   = blockIdx.y * 128;
    const int n0   = blockIdx.x * 128;

    const uint32_t* Ap[3] = { (const uint32_t*)(A0 + blockIdx.z*sA),
                              (const uint32_t*)(A1 ? A1 + blockIdx.z*sA : A0),
                              (const uint32_t*)(A2 ? A2 + blockIdx.z*sA : A0) };
    const uint32_t* Bp[3] = { (const uint32_t*)(B0 + blockIdx.z*sB),
                              (const uint32_t*)(B1 ? B1 + blockIdx.z*sB : B0),
                              (const uint32_t*)(B2 ? B2 + blockIdx.z*sB : B0) };
    Cout += blockIdx.z * sC;

    float c[2][8][4];
    #pragma unroll
    for (int i = 0; i < 2; i++)
        #pragma unroll
        for (int j = 0; j < 8; j++)
            #pragma unroll
            for (int k = 0; k < 4; k++) c[i][j][k] = 0.f;

    const int lda2 = lda >> 1, ldb2 = ldb >> 1;
    const int nchunk = Kdim >> 6;
    const int npairs = (NSPLIT == 2) ? 3 : 6;
    const int pa[6] = {0,0,1,1,0,2};
    const int pb[6] = {0,1,0,1,2,0};

    // ldmatrix lane-address components
    const int a_row_in = (lane & 15);
    const int a_cadd   = (lane >> 4) << 2;
    const int b_row_in = (lane & 7) + ((lane >> 4) << 3);
    const int b_cadd   = ((lane >> 3) & 1) << 2;

    for (int cc = 0; cc < nchunk; cc++) {
        if (cc) __syncthreads();
        int kb = cc << 5;
        #pragma unroll
        for (int p = 0; p < NSPLIT; p++) {
            const uint32_t* srcA = Ap[p];
            const uint32_t* srcB = Bp[p];
            #pragma unroll
            for (int i = 0; i < 16; i++) {
                int idx = t + (i << 8);
                int r = idx >> 5, col = idx & 31;
                Asm[p*PLANE + r*PITCH + col] = srcA[(size_t)(m0 + r)*lda2 + kb + col];
                Bsm[p*PLANE + r*PITCH + col] = srcB[(size_t)(n0 + r)*ldb2 + kb + col];
            }
        }
        __syncthreads();

        #pragma unroll
        for (int ks = 0; ks < 4; ks++) {
            // hoist A fragments for ALL planes (reused across pairs; pair
            // order below unchanged -> bitwise-identical accumulation)
            uint32_t af[NSPLIT][2][4];
            #pragma unroll
            for (int p = 0; p < NSPLIT; p++) {
                uint32_t abase = sbase + 4*(p*PLANE);
                #pragma unroll
                for (int mt = 0; mt < 2; mt++) {
                    int row = wm*32 + mt*16 + a_row_in;
                    ldm_x4(af[p][mt], abase + 4*(row*PITCH + ks*8 + a_cadd));
                }
            }
            #pragma unroll 6
            for (int pp = 0; pp < npairs; pp++) {
                uint32_t bbase = sbase + 4*((NSPLIT + pb[pp])*PLANE);
                uint32_t bf[8][2];
                #pragma unroll
                for (int nt2 = 0; nt2 < 4; nt2++) {
                    int row = wn*64 + nt2*16 + b_row_in;
                    uint32_t r4[4];
                    ldm_x4(r4, bbase + 4*(row*PITCH + ks*8 + b_cadd));
                    bf[nt2*2+0][0] = r4[0]; bf[nt2*2+0][1] = r4[1];
                    bf[nt2*2+1][0] = r4[2]; bf[nt2*2+1][1] = r4[3];
                }
                #pragma unroll
                for (int mt = 0; mt < 2; mt++)
                    #pragma unroll
                    for (int nt = 0; nt < 8; nt++)
                        mma16816(c[mt][nt], af[pa[pp]][mt], bf[nt]);
            }
        }
    }

    // epilogue
    #pragma unroll
    for (int mt = 0; mt < 2; mt++) {
        #pragma unroll
        for (int half = 0; half < 2; half++) {
            int m = m0 + wm*32 + mt*16 + g + half*8;
            #pragma unroll
            for (int nt = 0; nt < 8; nt++) {
                int n = n0 + wn*64 + nt*8 + tq*2;
                float2 r;
                r.x = alpha*c[mt][nt][half*2+0] + (bias ? bias[n]   : 0.f);
                r.y = alpha*c[mt][nt][half*2+1] + (bias ? bias[n+1] : 0.f);
                float* dst = headmajor ? (Cout + hm_dest(m, n))
                                       : (Cout + (size_t)m*ldc + n);
                *(float2*)dst = r;
            }
        }
    }
}

// ---------------------------------------------------------------------------
// High-accuracy two-level (Kahan) GEMM — Q AND K projections in ONE launch
// (blockIdx.z: 0=Q, 1=K) to fix wave quantization (512 -> 1024 blocks).
// Per-thread numeric sequence identical to rounds 6-11.
// ---------------------------------------------------------------------------
__global__ __launch_bounds__(256) void gemm_2lvl_qk(
    const float* __restrict__ A, int lda,
    const float* __restrict__ Wq, const float* __restrict__ Wk,
    const float* __restrict__ bq, const float* __restrict__ bk,
    __nv_bfloat16* __restrict__ Qhp, __nv_bfloat16* __restrict__ Qmp,
    __nv_bfloat16* __restrict__ Qlp,
    __nv_bfloat16* __restrict__ Khp, __nv_bfloat16* __restrict__ Kmp,
    __nv_bfloat16* __restrict__ Klp, int Kdim)
{
    const float* W    = blockIdx.z ? Wk : Wq;
    const float* bias = blockIdx.z ? bk : bq;
    __nv_bfloat16* Phi  = blockIdx.z ? Khp : Qhp;
    __nv_bfloat16* Pmid = blockIdx.z ? Kmp : Qmp;
    __nv_bfloat16* Plo  = blockIdx.z ? Klp : Qlp;

    __shared__ float As[2][16][128];
    __shared__ float Ws[2][16][64];
    int t  = threadIdx.x;
    int m0 = blockIdx.y * 128;
    int n0 = blockIdx.x * 64;
    int tm = t >> 4, tn = t & 15;
    int lr = t >> 2;
    int lc = (t & 3) << 2;

    float acc[8][4], cmp[8][4];
    #pragma unroll
    for (int i = 0; i < 8; i++)
        #pragma unroll
        for (int j = 0; j < 4; j++) { acc[i][j] = 0.f; cmp[i][j] = 0.f; }

    float4 a0, a1, w0;
    a0 = *(const float4*)(A + (size_t)(m0+lr   )*lda + lc);
    a1 = *(const float4*)(A + (size_t)(m0+lr+64)*lda + lc);
    w0 = *(const float4*)(W + (size_t)(n0+lr   )*lda + lc);
    As[0][lc+0][lr]    = a0.x; As[0][lc+1][lr]    = a0.y; As[0][lc+2][lr]    = a0.z; As[0][lc+3][lr]    = a0.w;
    As[0][lc+0][lr+64] = a1.x; As[0][lc+1][lr+64] = a1.y; As[0][lc+2][lr+64] = a1.z; As[0][lc+3][lr+64] = a1.w;
    Ws[0][lc+0][lr]    = w0.x; Ws[0][lc+1][lr]    = w0.y; Ws[0][lc+2][lr]    = w0.z; Ws[0][lc+3][lr]    = w0.w;
    __syncthreads();

    int nt = Kdim >> 4;
    for (int it = 0; it < nt; it++) {
        int cur = it & 1;
        if (it + 1 < nt) {
            int k0 = (it + 1) << 4;
            a0 = *(const float4*)(A + (size_t)(m0+lr   )*lda + k0 + lc);
            a1 = *(const float4*)(A + (size_t)(m0+lr+64)*lda + k0 + lc);
            w0 = *(const float4*)(W + (size_t)(n0+lr   )*lda + k0 + lc);
        }
        float tmp[8][4];
        #pragma unroll
        for (int i = 0; i < 8; i++)
            #pragma unroll
            for (int j = 0; j < 4; j++) tmp[i][j] = 0.f;
        #pragma unroll
        for (int kk = 0; kk < 16; kk++) {
            float a[8], bb[4];
            *(float4*)(a)    = *(const float4*)&As[cur][kk][tm*8];
            *(float4*)(a+4)  = *(const float4*)&As[cur][kk][tm*8+4];
            *(float4*)(bb)   = *(const float4*)&Ws[cur][kk][tn*4];
            #pragma unroll
            for (int i = 0; i < 8; i++)
                #pragma unroll
                for (int j = 0; j < 4; j++)
                    tmp[i][j] = fmaf(a[i], bb[j], tmp[i][j]);
        }
        #pragma unroll
        for (int i = 0; i < 8; i++)
            #pragma unroll
            for (int j = 0; j < 4; j++) {
                float y = tmp[i][j] - cmp[i][j];
                float s = acc[i][j] + y;
                cmp[i][j] = (s - acc[i][j]) - y;
                acc[i][j] = s;
            }
        if (it + 1 < nt) {
            int nx = (it + 1) & 1;
            As[nx][lc+0][lr]    = a0.x; As[nx][lc+1][lr]    = a0.y; As[nx][lc+2][lr]    = a0.z; As[nx][lc+3][lr]    = a0.w;
            As[nx][lc+0][lr+64] = a1.x; As[nx][lc+1][lr+64] = a1.y; As[nx][lc+2][lr+64] = a1.z; As[nx][lc+3][lr+64] = a1.w;
            Ws[nx][lc+0][lr]    = w0.x; Ws[nx][lc+1][lr]    = w0.y; Ws[nx][lc+2][lr]    = w0.z; Ws[nx][lc+3][lr]    = w0.w;
            __syncthreads();
        }
    }
    #pragma unroll
    for (int i = 0; i < 8; i++) {
        int m = m0 + tm*8 + i;
        int n = n0 + tn*4;
        size_t di = hm_dest(m, n);
        #pragma unroll
        for (int j = 0; j < 4; j++) {
            float v = acc[i][j] + bias[n+j];
            __nv_bfloat16 h = __float2bfloat16(v);
            float r1 = v - __bfloat162float(h);
            __nv_bfloat16 md = __float2bfloat16(r1);
            float r2 = r1 - __bfloat162float(md);
            Phi[di+j]  = h;
            Pmid[di+j] = md;
            Plo[di+j]  = __float2bfloat16(r2);
        }
    }
}

// ---------------------------------------------------------------------------
// Select kernel (unchanged round-8/10/11 passing logic).
// ---------------------------------------------------------------------------
__global__ __launch_bounds__(256) void select_kernel(
    const float* __restrict__ S, const float* __restrict__ V,
    __nv_bfloat16* __restrict__ Chi, __nv_bfloat16* __restrict__ Clo)
{
    int t    = threadIdx.x;
    int qq   = t >> 5;
    int lane = t & 31;
    int bh   = blockIdx.y;
    int b    = bh >> 4, h = bh & 15;
    int q    = blockIdx.x * QB + qq;

    const float4* Srow = (const float4*)(S + ((size_t)bh*SEQ + q)*SEQ);

    unsigned u[64];
    unsigned umax = 0u;
    unsigned c0=0,c1=0,c2=0,c3=0,c4=0,c5=0;
    #pragma unroll
    for (int i = 0; i < 16; i++) {
        float4 v = Srow[i*32 + lane];
        unsigned uu[4] = { f2u(v.x), f2u(v.y), f2u(v.z), f2u(v.w) };
        #pragma unroll
        for (int s = 0; s < 4; s++) {
            unsigned w = uu[s];
            u[4*i+s] = w;
            if (w > c5) {
                c5 = w;
                if (c5 > c4) { unsigned x=c4; c4=c5; c5=x; }
                if (c4 > c3) { unsigned x=c3; c3=c4; c4=x; }
                if (c3 > c2) { unsigned x=c2; c2=c3; c3=x; }
                if (c2 > c1) { unsigned x=c1; c1=c2; c2=x; }
                if (c1 > c0) { unsigned x=c0; c0=c1; c1=x; }
            }
        }
    }
    umax = c0;
    #pragma unroll
    for (int o = 16; o; o >>= 1)
        umax = max(umax, __shfl_xor_sync(0xffffffffu, umax, o));

    unsigned lo = 0u, hi = umax;
    while (lo < hi) {
        unsigned d   = hi - lo;
        unsigned mid = lo + (d >> 1) + (d & 1u);
        int c = (c0>=mid) + (c1>=mid) + (c2>=mid) + (c3>=mid) + (c4>=mid) + (c5>=mid);
        #pragma unroll
        for (int o = 16; o; o >>= 1) c += __shfl_xor_sync(0xffffffffu, c, o);
        if (c >= UTOP) lo = mid; else hi = mid - 1;
    }
    unsigned uth = lo;
    {
        int pack = 0;
        #pragma unroll
        for (int j = 0; j < 64; j++) {
            pack += (u[j] >= uth) ? 1 : 0;
            pack += (u[j] >  uth) ? (1 << 16) : 0;
        }
        #pragma unroll
        for (int o = 16; o; o >>= 1) pack += __shfl_xor_sync(0xffffffffu, pack, o);
        int cge = pack & 0xFFFF, cgt = pack >> 16;
        if (!(cge >= UTOP && cgt < UTOP)) {
            lo = 0u; hi = umax;
            while (lo < hi) {
                unsigned d   = hi - lo;
                unsigned mid = lo + (d >> 1) + (d & 1u);
                int c = 0;
                #pragma unroll
                for (int j = 0; j < 64; j++) c += (u[j] >= mid) ? 1 : 0;
                #pragma unroll
                for (int o = 16; o; o >>= 1) c += __shfl_xor_sync(0xffffffffu, c, o);
                if (c >= UTOP) lo = mid; else hi = mid - 1;
            }
            uth = lo;
        }
    }
    const float mymax = u2f(umax);

    const float* Vb = V + ((size_t)bh*SEQ)*HD;
    float sum = 0.f, acc0 = 0.f, acc1 = 0.f;
    #pragma unroll
    for (int j = 0; j < 64; j++) {
        bool keep = (u[j] >= uth);
        float p = keep ? __expf(u2f(u[j]) - mymax) : 0.f;
        sum += p;
        unsigned msk = __ballot_sync(0xffffffffu, keep);
        int kb = ((j >> 2) << 7) + (j & 3);
        while (msk) {
            int src = __ffs(msk) - 1; msk &= msk - 1;
            float pb = __shfl_sync(0xffffffffu, p, src);
            const float* vr = Vb + (size_t)(kb + (src << 2))*HD;
            acc0 = fmaf(pb, vr[lane],      acc0);
            acc1 = fmaf(pb, vr[lane + 32], acc1);
        }
    }
    #pragma unroll
    for (int o = 16; o; o >>= 1) sum += __shfl_xor_sync(0xffffffffu, sum, o);
    float inv = 1.f / sum;

    size_t o0 = ((size_t)(b*SEQ + q))*DM + h*HD;
    float v0 = acc0 * inv, v1 = acc1 * inv;
    __nv_bfloat16 h0 = __float2bfloat16(v0);
    __nv_bfloat16 h1 = __float2bfloat16(v1);
    Chi[o0 + lane]      = h0;
    Clo[o0 + lane]      = __float2bfloat16(v0 - __bfloat162float(h0));
    Chi[o0 + lane + 32] = h1;
    Clo[o0 + lane + 32] = __float2bfloat16(v1 - __bfloat162float(h1));
}

// ---------------------------------------------------------------------------
extern "C" void kernel_launch(void* const* d_in, const int* in_sizes, int n_in,
                              void* d_out, int out_size)
{
    const float* x  = (const float*)d_in[0];
    const float* Wq = (const float*)d_in[1];
    const float* bq = (const float*)d_in[2];
    const float* Wk = (const float*)d_in[3];
    const float* bk = (const float*)d_in[4];
    const float* Wv = (const float*)d_in[5];
    const float* bv = (const float*)d_in[6];
    const float* Wo = (const float*)d_in[7];
    const float* bo = (const float*)d_in[8];
    float* out = (float*)d_out;

    float *Sp, *Vp;
    __nv_bfloat16 *xh,*xl,*Wvh,*Wvl,*Woh,*Wol,*Qh,*Qm,*Ql,*Kh,*Km,*Kl,*Ch,*Cl;
    cudaGetSymbolAddress((void**)&Sp,  g_S);
    cudaGetSymbolAddress((void**)&Vp,  g_V);
    cudaGetSymbolAddress((void**)&xh,  g_xh);  cudaGetSymbolAddress((void**)&xl,  g_xl);
    cudaGetSymbolAddress((void**)&Wvh, g_Wvh); cudaGetSymbolAddress((void**)&Wvl, g_Wvl);
    cudaGetSymbolAddress((void**)&Woh, g_Woh); cudaGetSymbolAddress((void**)&Wol, g_Wol);
    cudaGetSymbolAddress((void**)&Qh,  g_Qh);  cudaGetSymbolAddress((void**)&Qm,  g_Qm);
    cudaGetSymbolAddress((void**)&Ql,  g_Ql);
    cudaGetSymbolAddress((void**)&Kh,  g_Kh);  cudaGetSymbolAddress((void**)&Km,  g_Km);
    cudaGetSymbolAddress((void**)&Kl,  g_Kl);
    cudaGetSymbolAddress((void**)&Ch,  g_Ch);  cudaGetSymbolAddress((void**)&Cl,  g_Cl);

    const int SM2 = 2*2*PLANE*4;   // 73728 B
    const int SM3 = 3*2*PLANE*4;   // 110592 B
    cudaFuncSetAttribute(gemm_mma<2>, cudaFuncAttributeMaxDynamicSharedMemorySize, SM2);
    cudaFuncSetAttribute(gemm_mma<3>, cudaFuncAttributeMaxDynamicSharedMemorySize, SM3);

    const int M = BATCH * SEQ;   // 4096

    // input splits
    split2_kernel<<<NELM/256, 256>>>(x, xh, xl, NELM);
    split2_kernel<<<DM*DM/256, 256>>>(Wv, Wvh, Wvl, DM*DM);
    split2_kernel<<<DM*DM/256, 256>>>(Wo, Woh, Wol, DM*DM);

    // Q + K projections in one launch (Kahan FFMA, bf16x3 planes out)
    gemm_2lvl_qk<<<dim3(DM/64, M/128, 2), 256>>>(x, DM, Wq, Wk, bq, bk,
                                                 Qh, Qm, Ql, Kh, Km, Kl, DM);

    // V projection (mma+ldmatrix, bf16x2, head-major fp32 out)
    gemm_mma<2><<<dim3(DM/128, M/128, 1), 256, SM2>>>(
        xh, xl, (const __nv_bfloat16*)0, DM, 0,
        Wvh, Wvl, (const __nv_bfloat16*)0, DM, 0,
        bv, Vp, 0, 0, DM, 1.f, 1);

    // Scores (mma+ldmatrix, bf16x3): S[bh] = 0.125 * Q[bh] @ K[bh]^T
    gemm_mma<3><<<dim3(SEQ/128, SEQ/128, BATCH*NH), 256, SM3>>>(
        Qh, Qm, Ql, HD, (size_t)SEQ*HD,
        Kh, Km, Kl, HD, (size_t)SEQ*HD,
        (const float*)0, Sp, SEQ, (size_t)SEQ*SEQ, HD, 0.125f, 0);

    // Top-38 select + softmax + sparse AV (context emitted as bf16 hi/lo)
    select_kernel<<<dim3(SEQ/QB, BATCH*NH), 256>>>(Sp, Vp, Ch, Cl);

    // Output projection (mma+ldmatrix, bf16x2)
    gemm_mma<2><<<dim3(DM/128, M/128, 1), 256, SM2>>>(
        Ch, Cl, (const __nv_bfloat16*)0, DM, 0,
        Woh, Wol, (const __nv_bfloat16*)0, DM, 0,
        bo, out, DM, 0, DM, 1.f, 0);
}

// round 15
// speedup vs baseline: 1.0990x; 1.0990x over previous
#include <cuda_runtime.h>
#include <cuda_bf16.h>
#include <math.h>
#include <stdint.h>

#define BATCH 2
#define SEQ   2048
#define DM    1024
#define NH    16
#define HD    64
#define UTOP  38
#define QB    8
#define NELM  (BATCH*SEQ*DM)   // 4194304

// ---------------------------------------------------------------------------
// Scratch (allocation-free rule: __device__ globals)
// ---------------------------------------------------------------------------
__device__ float g_S[(size_t)BATCH*NH*SEQ*SEQ];   // 536 MB score matrix
__device__ float g_V[BATCH*NH*SEQ*HD];            // V, head-major fp32
__device__ __nv_bfloat16 g_xh[NELM],  g_xl[NELM];
__device__ __nv_bfloat16 g_Wvh[DM*DM], g_Wvl[DM*DM];
__device__ __nv_bfloat16 g_Woh[DM*DM], g_Wol[DM*DM];
__device__ __nv_bfloat16 g_Qh[NELM], g_Qm[NELM], g_Ql[NELM];   // head-major
__device__ __nv_bfloat16 g_Kh[NELM], g_Km[NELM], g_Kl[NELM];   // head-major
__device__ __nv_bfloat16 g_Ch[NELM], g_Cl[NELM];               // context hi/lo

// ---------------------------------------------------------------------------
// helpers
// ---------------------------------------------------------------------------
__device__ __forceinline__ unsigned f2u(float f) {
    unsigned u = __float_as_uint(f);
    return (u & 0x80000000u) ? ~u : (u | 0x80000000u);
}
__device__ __forceinline__ float u2f(unsigned m) {
    return __uint_as_float((m & 0x80000000u) ? (m & 0x7FFFFFFFu) : ~m);
}
__device__ __forceinline__ size_t hm_dest(int m, int n) {
    int b = m >> 11, q = m & (SEQ-1);
    int h = n >> 6,  d = n & (HD-1);
    return ((size_t)b << 21) + ((size_t)h << 17) + ((size_t)q << 6) + d;
}
__device__ __forceinline__ uint32_t smem_to_u32(const void* p) {
    uint32_t a;
    asm("{ .reg .u64 tmp; cvta.to.shared.u64 tmp, %1; cvt.u32.u64 %0, tmp; }"
        : "=r"(a) : "l"(p));
    return a;
}

// m16n8k16 bf16 MMA, fp32 accumulate (arch-neutral PTX -> HMMA)
__device__ __forceinline__ void mma16816(float c[4], const uint32_t a[4],
                                         const uint32_t b[2]) {
    asm volatile(
        "mma.sync.aligned.m16n8k16.row.col.f32.bf16.bf16.f32 "
        "{%0,%1,%2,%3}, {%4,%5,%6,%7}, {%8,%9}, {%0,%1,%2,%3};"
        : "+f"(c[0]), "+f"(c[1]), "+f"(c[2]), "+f"(c[3])
        : "r"(a[0]), "r"(a[1]), "r"(a[2]), "r"(a[3]), "r"(b[0]), "r"(b[1]));
}
// ldmatrix x4 (arch-neutral, sm_75+)
__device__ __forceinline__ void ldm_x4(uint32_t r[4], uint32_t addr) {
    asm volatile("ldmatrix.sync.aligned.m8n8.x4.shared.b16 {%0,%1,%2,%3}, [%4];"
        : "=r"(r[0]), "=r"(r[1]), "=r"(r[2]), "=r"(r[3]) : "r"(addr));
}

// ---------------------------------------------------------------------------
// bf16 split kernel
// ---------------------------------------------------------------------------
__global__ void split2_kernel(const float* __restrict__ in,
                              __nv_bfloat16* __restrict__ hi,
                              __nv_bfloat16* __restrict__ lo, int n)
{
    int i = blockIdx.x * blockDim.x + threadIdx.x;
    if (i < n) {
        float v = in[i];
        __nv_bfloat16 h = __float2bfloat16(v);
        hi[i] = h;
        lo[i] = __float2bfloat16(v - __bfloat162float(h));
    }
}

// ---------------------------------------------------------------------------
// Tensor GEMM via mma.sync + ldmatrix — EXACT round-11 version (measured).
// Block tile 128x128, 8 warps (4m x 2n), warp tile 32x64, K chunks of 64.
// smem pitch 36 u32 (conflict-free ldmatrix).
// NSPLIT=2: pairs hh,hl,lh ; NSPLIT=3: hh,hm,mh,mm,hl,lh
// ---------------------------------------------------------------------------
#define PITCH 36
#define PLANE (128*PITCH)   // u32 per plane

template<int NSPLIT>
__global__ __launch_bounds__(256) void gemm_mma(
    const __nv_bfloat16* __restrict__ A0, const __nv_bfloat16* __restrict__ A1,
    const __nv_bfloat16* __restrict__ A2, int lda, size_t sA,
    const __nv_bfloat16* __restrict__ B0, const __nv_bfloat16* __restrict__ B1,
    const __nv_bfloat16* __restrict__ B2, int ldb, size_t sB,
    const float* __restrict__ bias,
    float* __restrict__ Cout, int ldc, size_t sC,
    int Kdim, float alpha, int headmajor)
{
    extern __shared__ uint32_t sm[];
    uint32_t* Asm = sm;                    // [NSPLIT][PLANE]
    uint32_t* Bsm = sm + NSPLIT*PLANE;     // [NSPLIT][PLANE]
    const uint32_t sbase = smem_to_u32(sm);

    const int t    = threadIdx.x;
    const int wid  = t >> 5, lane = t & 31;
    const int wm   = wid & 3, wn = wid >> 2;
    const int g    = lane >> 2;
    const int tq   = lane & 3;
    const int m0   = blockIdx.y * 128;
    const int n0   = blockIdx.x * 128;

    const uint32_t* Ap[3] = { (const uint32_t*)(A0 + blockIdx.z*sA),
                              (const uint32_t*)(A1 ? A1 + blockIdx.z*sA : A0),
                              (const uint32_t*)(A2 ? A2 + blockIdx.z*sA : A0) };
    const uint32_t* Bp[3] = { (const uint32_t*)(B0 + blockIdx.z*sB),
                              (const uint32_t*)(B1 ? B1 + blockIdx.z*sB : B0),
                              (const uint32_t*)(B2 ? B2 + blockIdx.z*sB : B0) };
    Cout += blockIdx.z * sC;

    float c[2][8][4];
    #pragma unroll
    for (int i = 0; i < 2; i++)
        #pragma unroll
        for (int j = 0; j < 8; j++)
            #pragma unroll
            for (int k = 0; k < 4; k++) c[i][j][k] = 0.f;

    const int lda2 = lda >> 1, ldb2 = ldb >> 1;
    const int nchunk = Kdim >> 6;
    const int npairs = (NSPLIT == 2) ? 3 : 6;
    const int pa[6] = {0,0,1,1,0,2};
    const int pb[6] = {0,1,0,1,2,0};

    // ldmatrix lane-address components
    const int a_row_in = (lane & 15);
    const int a_cadd   = (lane >> 4) << 2;
    const int b_row_in = (lane & 7) + ((lane >> 4) << 3);
    const int b_cadd   = ((lane >> 3) & 1) << 2;

    for (int cc = 0; cc < nchunk; cc++) {
        if (cc) __syncthreads();
        int kb = cc << 5;
        #pragma unroll
        for (int p = 0; p < NSPLIT; p++) {
            const uint32_t* srcA = Ap[p];
            const uint32_t* srcB = Bp[p];
            #pragma unroll
            for (int i = 0; i < 16; i++) {
                int idx = t + (i << 8);
                int r = idx >> 5, col = idx & 31;
                Asm[p*PLANE + r*PITCH + col] = srcA[(size_t)(m0 + r)*lda2 + kb + col];
                Bsm[p*PLANE + r*PITCH + col] = srcB[(size_t)(n0 + r)*ldb2 + kb + col];
            }
        }
        __syncthreads();

        #pragma unroll
        for (int ks = 0; ks < 4; ks++) {
            #pragma unroll 6
            for (int pp = 0; pp < npairs; pp++) {
                uint32_t abase = sbase + 4*(pa[pp]*PLANE);
                uint32_t bbase = sbase + 4*((NSPLIT + pb[pp])*PLANE);
                uint32_t af[2][4];
                #pragma unroll
                for (int mt = 0; mt < 2; mt++) {
                    int row = wm*32 + mt*16 + a_row_in;
                    ldm_x4(af[mt], abase + 4*(row*PITCH + ks*8 + a_cadd));
                }
                uint32_t bf[8][2];
                #pragma unroll
                for (int nt2 = 0; nt2 < 4; nt2++) {
                    int row = wn*64 + nt2*16 + b_row_in;
                    uint32_t r4[4];
                    ldm_x4(r4, bbase + 4*(row*PITCH + ks*8 + b_cadd));
                    bf[nt2*2+0][0] = r4[0]; bf[nt2*2+0][1] = r4[1];
                    bf[nt2*2+1][0] = r4[2]; bf[nt2*2+1][1] = r4[3];
                }
                #pragma unroll
                for (int mt = 0; mt < 2; mt++)
                    #pragma unroll
                    for (int nt = 0; nt < 8; nt++)
                        mma16816(c[mt][nt], af[mt], bf[nt]);
            }
        }
    }

    // epilogue
    #pragma unroll
    for (int mt = 0; mt < 2; mt++) {
        #pragma unroll
        for (int half = 0; half < 2; half++) {
            int m = m0 + wm*32 + mt*16 + g + half*8;
            #pragma unroll
            for (int nt = 0; nt < 8; nt++) {
                int n = n0 + wn*64 + nt*8 + tq*2;
                float2 r;
                r.x = alpha*c[mt][nt][half*2+0] + (bias ? bias[n]   : 0.f);
                r.y = alpha*c[mt][nt][half*2+1] + (bias ? bias[n+1] : 0.f);
                float* dst = headmajor ? (Cout + hm_dest(m, n))
                                       : (Cout + (size_t)m*ldc + n);
                *(float2*)dst = r;
            }
        }
    }
}

// ---------------------------------------------------------------------------
// High-accuracy two-level (Kahan) GEMM — Q AND K projections in ONE launch
// (blockIdx.z: 0=Q, 1=K). Measured 541us vs 616us for separate launches.
// Per-thread numeric sequence identical to rounds 6-14.
// ---------------------------------------------------------------------------
__global__ __launch_bounds__(256) void gemm_2lvl_qk(
    const float* __restrict__ A, int lda,
    const float* __restrict__ Wq, const float* __restrict__ Wk,
    const float* __restrict__ bq, const float* __restrict__ bk,
    __nv_bfloat16* __restrict__ Qhp, __nv_bfloat16* __restrict__ Qmp,
    __nv_bfloat16* __restrict__ Qlp,
    __nv_bfloat16* __restrict__ Khp, __nv_bfloat16* __restrict__ Kmp,
    __nv_bfloat16* __restrict__ Klp, int Kdim)
{
    const float* W    = blockIdx.z ? Wk : Wq;
    const float* bias = blockIdx.z ? bk : bq;
    __nv_bfloat16* Phi  = blockIdx.z ? Khp : Qhp;
    __nv_bfloat16* Pmid = blockIdx.z ? Kmp : Qmp;
    __nv_bfloat16* Plo  = blockIdx.z ? Klp : Qlp;

    __shared__ float As[2][16][128];
    __shared__ float Ws[2][16][64];
    int t  = threadIdx.x;
    int m0 = blockIdx.y * 128;
    int n0 = blockIdx.x * 64;
    int tm = t >> 4, tn = t & 15;
    int lr = t >> 2;
    int lc = (t & 3) << 2;

    float acc[8][4], cmp[8][4];
    #pragma unroll
    for (int i = 0; i < 8; i++)
        #pragma unroll
        for (int j = 0; j < 4; j++) { acc[i][j] = 0.f; cmp[i][j] = 0.f; }

    float4 a0, a1, w0;
    a0 = *(const float4*)(A + (size_t)(m0+lr   )*lda + lc);
    a1 = *(const float4*)(A + (size_t)(m0+lr+64)*lda + lc);
    w0 = *(const float4*)(W + (size_t)(n0+lr   )*lda + lc);
    As[0][lc+0][lr]    = a0.x; As[0][lc+1][lr]    = a0.y; As[0][lc+2][lr]    = a0.z; As[0][lc+3][lr]    = a0.w;
    As[0][lc+0][lr+64] = a1.x; As[0][lc+1][lr+64] = a1.y; As[0][lc+2][lr+64] = a1.z; As[0][lc+3][lr+64] = a1.w;
    Ws[0][lc+0][lr]    = w0.x; Ws[0][lc+1][lr]    = w0.y; Ws[0][lc+2][lr]    = w0.z; Ws[0][lc+3][lr]    = w0.w;
    __syncthreads();

    int nt = Kdim >> 4;
    for (int it = 0; it < nt; it++) {
        int cur = it & 1;
        if (it + 1 < nt) {
            int k0 = (it + 1) << 4;
            a0 = *(const float4*)(A + (size_t)(m0+lr   )*lda + k0 + lc);
            a1 = *(const float4*)(A + (size_t)(m0+lr+64)*lda + k0 + lc);
            w0 = *(const float4*)(W + (size_t)(n0+lr   )*lda + k0 + lc);
        }
        float tmp[8][4];
        #pragma unroll
        for (int i = 0; i < 8; i++)
            #pragma unroll
            for (int j = 0; j < 4; j++) tmp[i][j] = 0.f;
        #pragma unroll
        for (int kk = 0; kk < 16; kk++) {
            float a[8], bb[4];
            *(float4*)(a)    = *(const float4*)&As[cur][kk][tm*8];
            *(float4*)(a+4)  = *(const float4*)&As[cur][kk][tm*8+4];
            *(float4*)(bb)   = *(const float4*)&Ws[cur][kk][tn*4];
            #pragma unroll
            for (int i = 0; i < 8; i++)
                #pragma unroll
                for (int j = 0; j < 4; j++)
                    tmp[i][j] = fmaf(a[i], bb[j], tmp[i][j]);
        }
        #pragma unroll
        for (int i = 0; i < 8; i++)
            #pragma unroll
            for (int j = 0; j < 4; j++) {
                float y = tmp[i][j] - cmp[i][j];
                float s = acc[i][j] + y;
                cmp[i][j] = (s - acc[i][j]) - y;
                acc[i][j] = s;
            }
        if (it + 1 < nt) {
            int nx = (it + 1) & 1;
            As[nx][lc+0][lr]    = a0.x; As[nx][lc+1][lr]    = a0.y; As[nx][lc+2][lr]    = a0.z; As[nx][lc+3][lr]    = a0.w;
            As[nx][lc+0][lr+64] = a1.x; As[nx][lc+1][lr+64] = a1.y; As[nx][lc+2][lr+64] = a1.z; As[nx][lc+3][lr+64] = a1.w;
            Ws[nx][lc+0][lr]    = w0.x; Ws[nx][lc+1][lr]    = w0.y; Ws[nx][lc+2][lr]    = w0.z; Ws[nx][lc+3][lr]    = w0.w;
            __syncthreads();
        }
    }
    #pragma unroll
    for (int i = 0; i < 8; i++) {
        int m = m0 + tm*8 + i;
        int n = n0 + tn*4;
        size_t di = hm_dest(m, n);
        #pragma unroll
        for (int j = 0; j < 4; j++) {
            float v = acc[i][j] + bias[n+j];
            __nv_bfloat16 h = __float2bfloat16(v);
            float r1 = v - __bfloat162float(h);
            __nv_bfloat16 md = __float2bfloat16(r1);
            float r2 = r1 - __bfloat162float(md);
            Phi[di+j]  = h;
            Pmid[di+j] = md;
            Plo[di+j]  = __float2bfloat16(r2);
        }
    }
}

// ---------------------------------------------------------------------------
// Select kernel (unchanged round-8/10/11 passing logic).
// ---------------------------------------------------------------------------
__global__ __launch_bounds__(256) void select_kernel(
    const float* __restrict__ S, const float* __restrict__ V,
    __nv_bfloat16* __restrict__ Chi, __nv_bfloat16* __restrict__ Clo)
{
    int t    = threadIdx.x;
    int qq   = t >> 5;
    int lane = t & 31;
    int bh   = blockIdx.y;
    int b    = bh >> 4, h = bh & 15;
    int q    = blockIdx.x * QB + qq;

    const float4* Srow = (const float4*)(S + ((size_t)bh*SEQ + q)*SEQ);

    unsigned u[64];
    unsigned umax = 0u;
    unsigned c0=0,c1=0,c2=0,c3=0,c4=0,c5=0;
    #pragma unroll
    for (int i = 0; i < 16; i++) {
        float4 v = Srow[i*32 + lane];
        unsigned uu[4] = { f2u(v.x), f2u(v.y), f2u(v.z), f2u(v.w) };
        #pragma unroll
        for (int s = 0; s < 4; s++) {
            unsigned w = uu[s];
            u[4*i+s] = w;
            if (w > c5) {
                c5 = w;
                if (c5 > c4) { unsigned x=c4; c4=c5; c5=x; }
                if (c4 > c3) { unsigned x=c3; c3=c4; c4=x; }
                if (c3 > c2) { unsigned x=c2; c2=c3; c3=x; }
                if (c2 > c1) { unsigned x=c1; c1=c2; c2=x; }
                if (c1 > c0) { unsigned x=c0; c0=c1; c1=x; }
            }
        }
    }
    umax = c0;
    #pragma unroll
    for (int o = 16; o; o >>= 1)
        umax = max(umax, __shfl_xor_sync(0xffffffffu, umax, o));

    unsigned lo = 0u, hi = umax;
    while (lo < hi) {
        unsigned d   = hi - lo;
        unsigned mid = lo + (d >> 1) + (d & 1u);
        int c = (c0>=mid) + (c1>=mid) + (c2>=mid) + (c3>=mid) + (c4>=mid) + (c5>=mid);
        #pragma unroll
        for (int o = 16; o; o >>= 1) c += __shfl_xor_sync(0xffffffffu, c, o);
        if (c >= UTOP) lo = mid; else hi = mid - 1;
    }
    unsigned uth = lo;
    {
        int pack = 0;
        #pragma unroll
        for (int j = 0; j < 64; j++) {
            pack += (u[j] >= uth) ? 1 : 0;
            pack += (u[j] >  uth) ? (1 << 16) : 0;
        }
        #pragma unroll
        for (int o = 16; o; o >>= 1) pack += __shfl_xor_sync(0xffffffffu, pack, o);
        int cge = pack & 0xFFFF, cgt = pack >> 16;
        if (!(cge >= UTOP && cgt < UTOP)) {
            lo = 0u; hi = umax;
            while (lo < hi) {
                unsigned d   = hi - lo;
                unsigned mid = lo + (d >> 1) + (d & 1u);
                int c = 0;
                #pragma unroll
                for (int j = 0; j < 64; j++) c += (u[j] >= mid) ? 1 : 0;
                #pragma unroll
                for (int o = 16; o; o >>= 1) c += __shfl_xor_sync(0xffffffffu, c, o);
                if (c >= UTOP) lo = mid; else hi = mid - 1;
            }
            uth = lo;
        }
    }
    const float mymax = u2f(umax);

    const float* Vb = V + ((size_t)bh*SEQ)*HD;
    float sum = 0.f, acc0 = 0.f, acc1 = 0.f;
    #pragma unroll
    for (int j = 0; j < 64; j++) {
        bool keep = (u[j] >= uth);
        float p = keep ? __expf(u2f(u[j]) - mymax) : 0.f;
        sum += p;
        unsigned msk = __ballot_sync(0xffffffffu, keep);
        int kb = ((j >> 2) << 7) + (j & 3);
        while (msk) {
            int src = __ffs(msk) - 1; msk &= msk - 1;
            float pb = __shfl_sync(0xffffffffu, p, src);
            const float* vr = Vb + (size_t)(kb + (src << 2))*HD;
            acc0 = fmaf(pb, vr[lane],      acc0);
            acc1 = fmaf(pb, vr[lane + 32], acc1);
        }
    }
    #pragma unroll
    for (int o = 16; o; o >>= 1) sum += __shfl_xor_sync(0xffffffffu, sum, o);
    float inv = 1.f / sum;

    size_t o0 = ((size_t)(b*SEQ + q))*DM + h*HD;
    float v0 = acc0 * inv, v1 = acc1 * inv;
    __nv_bfloat16 h0 = __float2bfloat16(v0);
    __nv_bfloat16 h1 = __float2bfloat16(v1);
    Chi[o0 + lane]      = h0;
    Clo[o0 + lane]      = __float2bfloat16(v0 - __bfloat162float(h0));
    Chi[o0 + lane + 32] = h1;
    Clo[o0 + lane + 32] = __float2bfloat16(v1 - __bfloat162float(h1));
}

// ---------------------------------------------------------------------------
extern "C" void kernel_launch(void* const* d_in, const int* in_sizes, int n_in,
                              void* d_out, int out_size)
{
    const float* x  = (const float*)d_in[0];
    const float* Wq = (const float*)d_in[1];
    const float* bq = (const float*)d_in[2];
    const float* Wk = (const float*)d_in[3];
    const float* bk = (const float*)d_in[4];
    const float* Wv = (const float*)d_in[5];
    const float* bv = (const float*)d_in[6];
    const float* Wo = (const float*)d_in[7];
    const float* bo = (const float*)d_in[8];
    float* out = (float*)d_out;

    float *Sp, *Vp;
    __nv_bfloat16 *xh,*xl,*Wvh,*Wvl,*Woh,*Wol,*Qh,*Qm,*Ql,*Kh,*Km,*Kl,*Ch,*Cl;
    cudaGetSymbolAddress((void**)&Sp,  g_S);
    cudaGetSymbolAddress((void**)&Vp,  g_V);
    cudaGetSymbolAddress((void**)&xh,  g_xh);  cudaGetSymbolAddress((void**)&xl,  g_xl);
    cudaGetSymbolAddress((void**)&Wvh, g_Wvh); cudaGetSymbolAddress((void**)&Wvl, g_Wvl);
    cudaGetSymbolAddress((void**)&Woh, g_Woh); cudaGetSymbolAddress((void**)&Wol, g_Wol);
    cudaGetSymbolAddress((void**)&Qh,  g_Qh);  cudaGetSymbolAddress((void**)&Qm,  g_Qm);
    cudaGetSymbolAddress((void**)&Ql,  g_Ql);
    cudaGetSymbolAddress((void**)&Kh,  g_Kh);  cudaGetSymbolAddress((void**)&Km,  g_Km);
    cudaGetSymbolAddress((void**)&Kl,  g_Kl);
    cudaGetSymbolAddress((void**)&Ch,  g_Ch);  cudaGetSymbolAddress((void**)&Cl,  g_Cl);

    const int SM2 = 2*2*PLANE*4;   // 73728 B
    const int SM3 = 3*2*PLANE*4;   // 110592 B
    cudaFuncSetAttribute(gemm_mma<2>, cudaFuncAttributeMaxDynamicSharedMemorySize, SM2);
    cudaFuncSetAttribute(gemm_mma<3>, cudaFuncAttributeMaxDynamicSharedMemorySize, SM3);

    const int M = BATCH * SEQ;   // 4096

    // input splits
    split2_kernel<<<NELM/256, 256>>>(x, xh, xl, NELM);
    split2_kernel<<<DM*DM/256, 256>>>(Wv, Wvh, Wvl, DM*DM);
    split2_kernel<<<DM*DM/256, 256>>>(Wo, Woh, Wol, DM*DM);

    // Q + K projections in one launch (Kahan FFMA, bf16x3 planes out)
    gemm_2lvl_qk<<<dim3(DM/64, M/128, 2), 256>>>(x, DM, Wq, Wk, bq, bk,
                                                 Qh, Qm, Ql, Kh, Km, Kl, DM);

    // V projection (mma+ldmatrix, bf16x2, head-major fp32 out)
    gemm_mma<2><<<dim3(DM/128, M/128, 1), 256, SM2>>>(
        xh, xl, (const __nv_bfloat16*)0, DM, 0,
        Wvh, Wvl, (const __nv_bfloat16*)0, DM, 0,
        bv, Vp, 0, 0, DM, 1.f, 1);

    // Scores (mma+ldmatrix, bf16x3): S[bh] = 0.125 * Q[bh] @ K[bh]^T
    gemm_mma<3><<<dim3(SEQ/128, SEQ/128, BATCH*NH), 256, SM3>>>(
        Qh, Qm, Ql, HD, (size_t)SEQ*HD,
        Kh, Km, Kl, HD, (size_t)SEQ*HD,
        (const float*)0, Sp, SEQ, (size_t)SEQ*SEQ, HD, 0.125f, 0);

    // Top-38 select + softmax + sparse AV (context emitted as bf16 hi/lo)
    select_kernel<<<dim3(SEQ/QB, BATCH*NH), 256>>>(Sp, Vp, Ch, Cl);

    // Output projection (mma+ldmatrix, bf16x2)
    gemm_mma<2><<<dim3(DM/128, M/128, 1), 256, SM2>>>(
        Ch, Cl, (const __nv_bfloat16*)0, DM, 0,
        Woh, Wol, (const __nv_bfloat16*)0, DM, 0,
        bo, out, DM, 0, DM, 1.f, 0);
}

// round 16
// speedup vs baseline: 1.1760x; 1.0701x over previous
#include <cuda_runtime.h>
#include <cuda_bf16.h>
#include <math.h>
#include <stdint.h>

#define BATCH 2
#define SEQ   2048
#define DM    1024
#define NH    16
#define HD    64
#define UTOP  38
#define QB    8
#define NELM  (BATCH*SEQ*DM)   // 4194304

// ---------------------------------------------------------------------------
// Scratch (allocation-free rule: __device__ globals)
// ---------------------------------------------------------------------------
__device__ float g_S[(size_t)BATCH*NH*SEQ*SEQ];   // 536 MB score matrix
__device__ float g_V[BATCH*NH*SEQ*HD];            // V, head-major fp32
__device__ __nv_bfloat16 g_xh[NELM],  g_xl[NELM];
__device__ __nv_bfloat16 g_Wvh[DM*DM], g_Wvl[DM*DM];
__device__ __nv_bfloat16 g_Woh[DM*DM], g_Wol[DM*DM];
__device__ __nv_bfloat16 g_Qh[NELM], g_Qm[NELM], g_Ql[NELM];   // head-major
__device__ __nv_bfloat16 g_Kh[NELM], g_Km[NELM], g_Kl[NELM];   // head-major
__device__ __nv_bfloat16 g_Ch[NELM], g_Cl[NELM];               // context hi/lo

// ---------------------------------------------------------------------------
// helpers
// ---------------------------------------------------------------------------
__device__ __forceinline__ unsigned f2u(float f) {
    unsigned u = __float_as_uint(f);
    return (u & 0x80000000u) ? ~u : (u | 0x80000000u);
}
__device__ __forceinline__ float u2f(unsigned m) {
    return __uint_as_float((m & 0x80000000u) ? (m & 0x7FFFFFFFu) : ~m);
}
__device__ __forceinline__ size_t hm_dest(int m, int n) {
    int b = m >> 11, q = m & (SEQ-1);
    int h = n >> 6,  d = n & (HD-1);
    return ((size_t)b << 21) + ((size_t)h << 17) + ((size_t)q << 6) + d;
}
__device__ __forceinline__ uint32_t smem_to_u32(const void* p) {
    uint32_t a;
    asm("{ .reg .u64 tmp; cvta.to.shared.u64 tmp, %1; cvt.u32.u64 %0, tmp; }"
        : "=r"(a) : "l"(p));
    return a;
}

// m16n8k16 bf16 MMA, fp32 accumulate (arch-neutral PTX -> HMMA)
__device__ __forceinline__ void mma16816(float c[4], const uint32_t a[4],
                                         const uint32_t b[2]) {
    asm volatile(
        "mma.sync.aligned.m16n8k16.row.col.f32.bf16.bf16.f32 "
        "{%0,%1,%2,%3}, {%4,%5,%6,%7}, {%8,%9}, {%0,%1,%2,%3};"
        : "+f"(c[0]), "+f"(c[1]), "+f"(c[2]), "+f"(c[3])
        : "r"(a[0]), "r"(a[1]), "r"(a[2]), "r"(a[3]), "r"(b[0]), "r"(b[1]));
}
// ldmatrix x4 (arch-neutral, sm_75+)
__device__ __forceinline__ void ldm_x4(uint32_t r[4], uint32_t addr) {
    asm volatile("ldmatrix.sync.aligned.m8n8.x4.shared.b16 {%0,%1,%2,%3}, [%4];"
        : "=r"(r[0]), "=r"(r[1]), "=r"(r[2]), "=r"(r[3]) : "r"(addr));
}
// 16B async copy global -> shared (L2-cached)
__device__ __forceinline__ void cp16(uint32_t smem_addr, const void* gptr) {
    asm volatile("cp.async.cg.shared.global [%0], [%1], 16;"
                 :: "r"(smem_addr), "l"(gptr) : "memory");
}

// ---------------------------------------------------------------------------
// bf16 split kernel
// ---------------------------------------------------------------------------
__global__ void split2_kernel(const float* __restrict__ in,
                              __nv_bfloat16* __restrict__ hi,
                              __nv_bfloat16* __restrict__ lo, int n)
{
    int i = blockIdx.x * blockDim.x + threadIdx.x;
    if (i < n) {
        float v = in[i];
        __nv_bfloat16 h = __float2bfloat16(v);
        hi[i] = h;
        lo[i] = __float2bfloat16(v - __bfloat162float(h));
    }
}

// ---------------------------------------------------------------------------
// Tensor GEMM via mma.sync + ldmatrix, cp.async-pipelined chunk loads.
// Math (pair order, fragment mapping, accumulation sequence) is byte-
// identical to the round-11/15 measured version -> bitwise-same outputs.
// Block tile 128x128, 8 warps (4m x 2n), warp tile 32x64, K chunks of 64.
// smem pitch 36 u32 (144B rows; 16B-aligned, conflict-free ldmatrix).
// NSTAGE=2: double-buffered chunks (V/O, nchunk=16).
// NSTAGE=1: single upfront async burst (score, nchunk=1).
// ---------------------------------------------------------------------------
#define PITCH 36
#define PLANE (128*PITCH)   // u32 per plane

template<int NSPLIT, int NSTAGE>
__global__ __launch_bounds__(256) void gemm_mma(
    const __nv_bfloat16* __restrict__ A0, const __nv_bfloat16* __restrict__ A1,
    const __nv_bfloat16* __restrict__ A2, int lda, size_t sA,
    const __nv_bfloat16* __restrict__ B0, const __nv_bfloat16* __restrict__ B1,
    const __nv_bfloat16* __restrict__ B2, int ldb, size_t sB,
    const float* __restrict__ bias,
    float* __restrict__ Cout, int ldc, size_t sC,
    int Kdim, float alpha, int headmajor)
{
    extern __shared__ uint32_t sm[];
    const uint32_t sbase = smem_to_u32(sm);
    const int STAGE_U = NSPLIT*2*PLANE;    // u32 per stage

    const int t    = threadIdx.x;
    const int wid  = t >> 5, lane = t & 31;
    const int wm   = wid & 3, wn = wid >> 2;
    const int g    = lane >> 2;
    const int tq   = lane & 3;
    const int m0   = blockIdx.y * 128;
    const int n0   = blockIdx.x * 128;

    const uint32_t* Ap[3] = { (const uint32_t*)(A0 + blockIdx.z*sA),
                              (const uint32_t*)(A1 ? A1 + blockIdx.z*sA : A0),
                              (const uint32_t*)(A2 ? A2 + blockIdx.z*sA : A0) };
    const uint32_t* Bp[3] = { (const uint32_t*)(B0 + blockIdx.z*sB),
                              (const uint32_t*)(B1 ? B1 + blockIdx.z*sB : B0),
                              (const uint32_t*)(B2 ? B2 + blockIdx.z*sB : B0) };
    Cout += blockIdx.z * sC;

    float c[2][8][4];
    #pragma unroll
    for (int i = 0; i < 2; i++)
        #pragma unroll
        for (int j = 0; j < 8; j++)
            #pragma unroll
            for (int k = 0; k < 4; k++) c[i][j][k] = 0.f;

    const int lda2 = lda >> 1, ldb2 = ldb >> 1;
    const int nchunk = Kdim >> 6;
    const int npairs = (NSPLIT == 2) ? 3 : 6;
    const int pa[6] = {0,0,1,1,0,2};
    const int pb[6] = {0,1,0,1,2,0};

    // per-thread cp.async assignment: 4 granules (16B) per plane-half
    const int gid_row  = t >> 3;          // reused: granule (t + i*256)
    const int gid_gcol = (t & 7) << 2;    // u32 col of granule base

    // chunk loader: all planes of chunk cc into stage s
    auto load_chunk = [&](int cc, int s) {
        int kb = cc << 5;
        int stU = s * STAGE_U;
        #pragma unroll
        for (int p = 0; p < NSPLIT; p++) {
            const uint32_t* srcA = Ap[p];
            const uint32_t* srcB = Bp[p];
            #pragma unroll
            for (int i = 0; i < 4; i++) {
                int gid  = t + (i << 8);            // 0..1023
                int row  = gid >> 3;
                int gcol = (gid & 7) << 2;
                cp16(sbase + 4*(stU + p*PLANE + row*PITCH + gcol),
                     srcA + (size_t)(m0 + row)*lda2 + kb + gcol);
                cp16(sbase + 4*(stU + (NSPLIT + p)*PLANE + row*PITCH + gcol),
                     srcB + (size_t)(n0 + row)*ldb2 + kb + gcol);
            }
        }
        asm volatile("cp.async.commit_group;" ::: "memory");
    };

    // ldmatrix lane-address components
    const int a_row_in = (lane & 15);
    const int a_cadd   = (lane >> 4) << 2;
    const int b_row_in = (lane & 7) + ((lane >> 4) << 3);
    const int b_cadd   = ((lane >> 3) & 1) << 2;

    load_chunk(0, 0);

    for (int cc = 0; cc < nchunk; cc++) {
        if (cc + 1 < nchunk) {
            load_chunk(cc + 1, (cc + 1) % NSTAGE);
            asm volatile("cp.async.wait_group 1;" ::: "memory");
        } else {
            asm volatile("cp.async.wait_group 0;" ::: "memory");
        }
        __syncthreads();

        int stU = (cc % NSTAGE) * STAGE_U;
        #pragma unroll
        for (int ks = 0; ks < 4; ks++) {
            #pragma unroll 6
            for (int pp = 0; pp < npairs; pp++) {
                uint32_t abase = sbase + 4*(stU + pa[pp]*PLANE);
                uint32_t bbase = sbase + 4*(stU + (NSPLIT + pb[pp])*PLANE);
                uint32_t af[2][4];
                #pragma unroll
                for (int mt = 0; mt < 2; mt++) {
                    int row = wm*32 + mt*16 + a_row_in;
                    ldm_x4(af[mt], abase + 4*(row*PITCH + ks*8 + a_cadd));
                }
                uint32_t bf[8][2];
                #pragma unroll
                for (int nt2 = 0; nt2 < 4; nt2++) {
                    int row = wn*64 + nt2*16 + b_row_in;
                    uint32_t r4[4];
                    ldm_x4(r4, bbase + 4*(row*PITCH + ks*8 + b_cadd));
                    bf[nt2*2+0][0] = r4[0]; bf[nt2*2+0][1] = r4[1];
                    bf[nt2*2+1][0] = r4[2]; bf[nt2*2+1][1] = r4[3];
                }
                #pragma unroll
                for (int mt = 0; mt < 2; mt++)
                    #pragma unroll
                    for (int nt = 0; nt < 8; nt++)
                        mma16816(c[mt][nt], af[mt], bf[nt]);
            }
        }
        __syncthreads();
    }

    // epilogue
    #pragma unroll
    for (int mt = 0; mt < 2; mt++) {
        #pragma unroll
        for (int half = 0; half < 2; half++) {
            int m = m0 + wm*32 + mt*16 + g + half*8;
            #pragma unroll
            for (int nt = 0; nt < 8; nt++) {
                int n = n0 + wn*64 + nt*8 + tq*2;
                float2 r;
                r.x = alpha*c[mt][nt][half*2+0] + (bias ? bias[n]   : 0.f);
                r.y = alpha*c[mt][nt][half*2+1] + (bias ? bias[n+1] : 0.f);
                float* dst = headmajor ? (Cout + hm_dest(m, n))
                                       : (Cout + (size_t)m*ldc + n);
                *(float2*)dst = r;
            }
        }
    }
}

// ---------------------------------------------------------------------------
// High-accuracy two-level (Kahan) GEMM — Q AND K projections in ONE launch
// (blockIdx.z: 0=Q, 1=K). Per-thread numeric sequence identical to rounds
// 6-15 (verified at FFMA roofline; do not touch).
// ---------------------------------------------------------------------------
__global__ __launch_bounds__(256) void gemm_2lvl_qk(
    const float* __restrict__ A, int lda,
    const float* __restrict__ Wq, const float* __restrict__ Wk,
    const float* __restrict__ bq, const float* __restrict__ bk,
    __nv_bfloat16* __restrict__ Qhp, __nv_bfloat16* __restrict__ Qmp,
    __nv_bfloat16* __restrict__ Qlp,
    __nv_bfloat16* __restrict__ Khp, __nv_bfloat16* __restrict__ Kmp,
    __nv_bfloat16* __restrict__ Klp, int Kdim)
{
    const float* W    = blockIdx.z ? Wk : Wq;
    const float* bias = blockIdx.z ? bk : bq;
    __nv_bfloat16* Phi  = blockIdx.z ? Khp : Qhp;
    __nv_bfloat16* Pmid = blockIdx.z ? Kmp : Qmp;
    __nv_bfloat16* Plo  = blockIdx.z ? Klp : Qlp;

    __shared__ float As[2][16][128];
    __shared__ float Ws[2][16][64];
    int t  = threadIdx.x;
    int m0 = blockIdx.y * 128;
    int n0 = blockIdx.x * 64;
    int tm = t >> 4, tn = t & 15;
    int lr = t >> 2;
    int lc = (t & 3) << 2;

    float acc[8][4], cmp[8][4];
    #pragma unroll
    for (int i = 0; i < 8; i++)
        #pragma unroll
        for (int j = 0; j < 4; j++) { acc[i][j] = 0.f; cmp[i][j] = 0.f; }

    float4 a0, a1, w0;
    a0 = *(const float4*)(A + (size_t)(m0+lr   )*lda + lc);
    a1 = *(const float4*)(A + (size_t)(m0+lr+64)*lda + lc);
    w0 = *(const float4*)(W + (size_t)(n0+lr   )*lda + lc);
    As[0][lc+0][lr]    = a0.x; As[0][lc+1][lr]    = a0.y; As[0][lc+2][lr]    = a0.z; As[0][lc+3][lr]    = a0.w;
    As[0][lc+0][lr+64] = a1.x; As[0][lc+1][lr+64] = a1.y; As[0][lc+2][lr+64] = a1.z; As[0][lc+3][lr+64] = a1.w;
    Ws[0][lc+0][lr]    = w0.x; Ws[0][lc+1][lr]    = w0.y; Ws[0][lc+2][lr]    = w0.z; Ws[0][lc+3][lr]    = w0.w;
    __syncthreads();

    int nt = Kdim >> 4;
    for (int it = 0; it < nt; it++) {
        int cur = it & 1;
        if (it + 1 < nt) {
            int k0 = (it + 1) << 4;
            a0 = *(const float4*)(A + (size_t)(m0+lr   )*lda + k0 + lc);
            a1 = *(const float4*)(A + (size_t)(m0+lr+64)*lda + k0 + lc);
            w0 = *(const float4*)(W + (size_t)(n0+lr   )*lda + k0 + lc);
        }
        float tmp[8][4];
        #pragma unroll
        for (int i = 0; i < 8; i++)
            #pragma unroll
            for (int j = 0; j < 4; j++) tmp[i][j] = 0.f;
        #pragma unroll
        for (int kk = 0; kk < 16; kk++) {
            float a[8], bb[4];
            *(float4*)(a)    = *(const float4*)&As[cur][kk][tm*8];
            *(float4*)(a+4)  = *(const float4*)&As[cur][kk][tm*8+4];
            *(float4*)(bb)   = *(const float4*)&Ws[cur][kk][tn*4];
            #pragma unroll
            for (int i = 0; i < 8; i++)
                #pragma unroll
                for (int j = 0; j < 4; j++)
                    tmp[i][j] = fmaf(a[i], bb[j], tmp[i][j]);
        }
        #pragma unroll
        for (int i = 0; i < 8; i++)
            #pragma unroll
            for (int j = 0; j < 4; j++) {
                float y = tmp[i][j] - cmp[i][j];
                float s = acc[i][j] + y;
                cmp[i][j] = (s - acc[i][j]) - y;
                acc[i][j] = s;
            }
        if (it + 1 < nt) {
            int nx = (it + 1) & 1;
            As[nx][lc+0][lr]    = a0.x; As[nx][lc+1][lr]    = a0.y; As[nx][lc+2][lr]    = a0.z; As[nx][lc+3][lr]    = a0.w;
            As[nx][lc+0][lr+64] = a1.x; As[nx][lc+1][lr+64] = a1.y; As[nx][lc+2][lr+64] = a1.z; As[nx][lc+3][lr+64] = a1.w;
            Ws[nx][lc+0][lr]    = w0.x; Ws[nx][lc+1][lr]    = w0.y; Ws[nx][lc+2][lr]    = w0.z; Ws[nx][lc+3][lr]    = w0.w;
            __syncthreads();
        }
    }
    #pragma unroll
    for (int i = 0; i < 8; i++) {
        int m = m0 + tm*8 + i;
        int n = n0 + tn*4;
        size_t di = hm_dest(m, n);
        #pragma unroll
        for (int j = 0; j < 4; j++) {
            float v = acc[i][j] + bias[n+j];
            __nv_bfloat16 h = __float2bfloat16(v);
            float r1 = v - __bfloat162float(h);
            __nv_bfloat16 md = __float2bfloat16(r1);
            float r2 = r1 - __bfloat162float(md);
            Phi[di+j]  = h;
            Pmid[di+j] = md;
            Plo[di+j]  = __float2bfloat16(r2);
        }
    }
}

// ---------------------------------------------------------------------------
// Select kernel (unchanged round-8/10/11/15 passing logic).
// ---------------------------------------------------------------------------
__global__ __launch_bounds__(256) void select_kernel(
    const float* __restrict__ S, const float* __restrict__ V,
    __nv_bfloat16* __restrict__ Chi, __nv_bfloat16* __restrict__ Clo)
{
    int t    = threadIdx.x;
    int qq   = t >> 5;
    int lane = t & 31;
    int bh   = blockIdx.y;
    int b    = bh >> 4, h = bh & 15;
    int q    = blockIdx.x * QB + qq;

    const float4* Srow = (const float4*)(S + ((size_t)bh*SEQ + q)*SEQ);

    unsigned u[64];
    unsigned umax = 0u;
    unsigned c0=0,c1=0,c2=0,c3=0,c4=0,c5=0;
    #pragma unroll
    for (int i = 0; i < 16; i++) {
        float4 v = Srow[i*32 + lane];
        unsigned uu[4] = { f2u(v.x), f2u(v.y), f2u(v.z), f2u(v.w) };
        #pragma unroll
        for (int s = 0; s < 4; s++) {
            unsigned w = uu[s];
            u[4*i+s] = w;
            if (w > c5) {
                c5 = w;
                if (c5 > c4) { unsigned x=c4; c4=c5; c5=x; }
                if (c4 > c3) { unsigned x=c3; c3=c4; c4=x; }
                if (c3 > c2) { unsigned x=c2; c2=c3; c3=x; }
                if (c2 > c1) { unsigned x=c1; c1=c2; c2=x; }
                if (c1 > c0) { unsigned x=c0; c0=c1; c1=x; }
            }
        }
    }
    umax = c0;
    #pragma unroll
    for (int o = 16; o; o >>= 1)
        umax = max(umax, __shfl_xor_sync(0xffffffffu, umax, o));

    unsigned lo = 0u, hi = umax;
    while (lo < hi) {
        unsigned d   = hi - lo;
        unsigned mid = lo + (d >> 1) + (d & 1u);
        int c = (c0>=mid) + (c1>=mid) + (c2>=mid) + (c3>=mid) + (c4>=mid) + (c5>=mid);
        #pragma unroll
        for (int o = 16; o; o >>= 1) c += __shfl_xor_sync(0xffffffffu, c, o);
        if (c >= UTOP) lo = mid; else hi = mid - 1;
    }
    unsigned uth = lo;
    {
        int pack = 0;
        #pragma unroll
        for (int j = 0; j < 64; j++) {
            pack += (u[j] >= uth) ? 1 : 0;
            pack += (u[j] >  uth) ? (1 << 16) : 0;
        }
        #pragma unroll
        for (int o = 16; o; o >>= 1) pack += __shfl_xor_sync(0xffffffffu, pack, o);
        int cge = pack & 0xFFFF, cgt = pack >> 16;
        if (!(cge >= UTOP && cgt < UTOP)) {
            lo = 0u; hi = umax;
            while (lo < hi) {
                unsigned d   = hi - lo;
                unsigned mid = lo + (d >> 1) + (d & 1u);
                int c = 0;
                #pragma unroll
                for (int j = 0; j < 64; j++) c += (u[j] >= mid) ? 1 : 0;
                #pragma unroll
                for (int o = 16; o; o >>= 1) c += __shfl_xor_sync(0xffffffffu, c, o);
                if (c >= UTOP) lo = mid; else hi = mid - 1;
            }
            uth = lo;
        }
    }
    const float mymax = u2f(umax);

    const float* Vb = V + ((size_t)bh*SEQ)*HD;
    float sum = 0.f, acc0 = 0.f, acc1 = 0.f;
    #pragma unroll
    for (int j = 0; j < 64; j++) {
        bool keep = (u[j] >= uth);
        float p = keep ? __expf(u2f(u[j]) - mymax) : 0.f;
        sum += p;
        unsigned msk = __ballot_sync(0xffffffffu, keep);
        int kb = ((j >> 2) << 7) + (j & 3);
        while (msk) {
            int src = __ffs(msk) - 1; msk &= msk - 1;
            float pb = __shfl_sync(0xffffffffu, p, src);
            const float* vr = Vb + (size_t)(kb + (src << 2))*HD;
            acc0 = fmaf(pb, vr[lane],      acc0);
            acc1 = fmaf(pb, vr[lane + 32], acc1);
        }
    }
    #pragma unroll
    for (int o = 16; o; o >>= 1) sum += __shfl_xor_sync(0xffffffffu, sum, o);
    float inv = 1.f / sum;

    size_t o0 = ((size_t)(b*SEQ + q))*DM + h*HD;
    float v0 = acc0 * inv, v1 = acc1 * inv;
    __nv_bfloat16 h0 = __float2bfloat16(v0);
    __nv_bfloat16 h1 = __float2bfloat16(v1);
    Chi[o0 + lane]      = h0;
    Clo[o0 + lane]      = __float2bfloat16(v0 - __bfloat162float(h0));
    Chi[o0 + lane + 32] = h1;
    Clo[o0 + lane + 32] = __float2bfloat16(v1 - __bfloat162float(h1));
}

// ---------------------------------------------------------------------------
extern "C" void kernel_launch(void* const* d_in, const int* in_sizes, int n_in,
                              void* d_out, int out_size)
{
    const float* x  = (const float*)d_in[0];
    const float* Wq = (const float*)d_in[1];
    const float* bq = (const float*)d_in[2];
    const float* Wk = (const float*)d_in[3];
    const float* bk = (const float*)d_in[4];
    const float* Wv = (const float*)d_in[5];
    const float* bv = (const float*)d_in[6];
    const float* Wo = (const float*)d_in[7];
    const float* bo = (const float*)d_in[8];
    float* out = (float*)d_out;

    float *Sp, *Vp;
    __nv_bfloat16 *xh,*xl,*Wvh,*Wvl,*Woh,*Wol,*Qh,*Qm,*Ql,*Kh,*Km,*Kl,*Ch,*Cl;
    cudaGetSymbolAddress((void**)&Sp,  g_S);
    cudaGetSymbolAddress((void**)&Vp,  g_V);
    cudaGetSymbolAddress((void**)&xh,  g_xh);  cudaGetSymbolAddress((void**)&xl,  g_xl);
    cudaGetSymbolAddress((void**)&Wvh, g_Wvh); cudaGetSymbolAddress((void**)&Wvl, g_Wvl);
    cudaGetSymbolAddress((void**)&Woh, g_Woh); cudaGetSymbolAddress((void**)&Wol, g_Wol);
    cudaGetSymbolAddress((void**)&Qh,  g_Qh);  cudaGetSymbolAddress((void**)&Qm,  g_Qm);
    cudaGetSymbolAddress((void**)&Ql,  g_Ql);
    cudaGetSymbolAddress((void**)&Kh,  g_Kh);  cudaGetSymbolAddress((void**)&Km,  g_Km);
    cudaGetSymbolAddress((void**)&Kl,  g_Kl);
    cudaGetSymbolAddress((void**)&Ch,  g_Ch);  cudaGetSymbolAddress((void**)&Cl,  g_Cl);

    const int SM2 = 2*2*2*PLANE*4;   // NSPLIT=2, NSTAGE=2: 147456 B
    const int SM3 = 3*2*1*PLANE*4;   // NSPLIT=3, NSTAGE=1: 110592 B
    cudaFuncSetAttribute((const void*)gemm_mma<2,2>,
                         cudaFuncAttributeMaxDynamicSharedMemorySize, SM2);
    cudaFuncSetAttribute((const void*)gemm_mma<3,1>,
                         cudaFuncAttributeMaxDynamicSharedMemorySize, SM3);

    const int M = BATCH * SEQ;   // 4096

    // input splits
    split2_kernel<<<NELM/256, 256>>>(x, xh, xl, NELM);
    split2_kernel<<<DM*DM/256, 256>>>(Wv, Wvh, Wvl, DM*DM);
    split2_kernel<<<DM*DM/256, 256>>>(Wo, Woh, Wol, DM*DM);

    // Q + K projections in one launch (Kahan FFMA, bf16x3 planes out)
    gemm_2lvl_qk<<<dim3(DM/64, M/128, 2), 256>>>(x, DM, Wq, Wk, bq, bk,
                                                 Qh, Qm, Ql, Kh, Km, Kl, DM);

    // V projection (mma+ldmatrix, bf16x2, cp.async 2-stage, head-major out)
    gemm_mma<2,2><<<dim3(DM/128, M/128, 1), 256, SM2>>>(
        xh, xl, (const __nv_bfloat16*)0, DM, 0,
        Wvh, Wvl, (const __nv_bfloat16*)0, DM, 0,
        bv, Vp, 0, 0, DM, 1.f, 1);

    // Scores (mma+ldmatrix, bf16x3, cp.async single burst)
    gemm_mma<3,1><<<dim3(SEQ/128, SEQ/128, BATCH*NH), 256, SM3>>>(
        Qh, Qm, Ql, HD, (size_t)SEQ*HD,
        Kh, Km, Kl, HD, (size_t)SEQ*HD,
        (const float*)0, Sp, SEQ, (size_t)SEQ*SEQ, HD, 0.125f, 0);

    // Top-38 select + softmax + sparse AV (context emitted as bf16 hi/lo)
    select_kernel<<<dim3(SEQ/QB, BATCH*NH), 256>>>(Sp, Vp, Ch, Cl);

    // Output projection (mma+ldmatrix, bf16x2, cp.async 2-stage)
    gemm_mma<2,2><<<dim3(DM/128, M/128, 1), 256, SM2>>>(
        Ch, Cl, (const __nv_bfloat16*)0, DM, 0,
        Woh, Wol, (const __nv_bfloat16*)0, DM, 0,
        bo, out, DM, 0, DM, 1.f, 0);
}

// round 17
// speedup vs baseline: 1.1921x; 1.0137x over previous
#include <cuda_runtime.h>
#include <cuda_bf16.h>
#include <math.h>
#include <stdint.h>

#define BATCH 2
#define SEQ   2048
#define DM    1024
#define NH    16
#define HD    64
#define UTOP  38
#define QB    8
#define NELM  (BATCH*SEQ*DM)   // 4194304

// ---------------------------------------------------------------------------
// Scratch (allocation-free rule: __device__ globals)
// ---------------------------------------------------------------------------
__device__ float g_S[(size_t)BATCH*NH*SEQ*SEQ];   // 536 MB score matrix
__device__ float g_V[BATCH*NH*SEQ*HD];            // V, head-major fp32
__device__ __nv_bfloat16 g_xh[NELM],  g_xl[NELM];
__device__ __nv_bfloat16 g_Wvh[DM*DM], g_Wvl[DM*DM];
__device__ __nv_bfloat16 g_Woh[DM*DM], g_Wol[DM*DM];
__device__ __nv_bfloat16 g_Qh[NELM], g_Qm[NELM], g_Ql[NELM];   // head-major
__device__ __nv_bfloat16 g_Kh[NELM], g_Km[NELM], g_Kl[NELM];   // head-major
__device__ __nv_bfloat16 g_Ch[NELM], g_Cl[NELM];               // context hi/lo

// ---------------------------------------------------------------------------
// helpers
// ---------------------------------------------------------------------------
__device__ __forceinline__ unsigned f2u(float f) {
    unsigned u = __float_as_uint(f);
    return (u & 0x80000000u) ? ~u : (u | 0x80000000u);
}
__device__ __forceinline__ float u2f(unsigned m) {
    return __uint_as_float((m & 0x80000000u) ? (m & 0x7FFFFFFFu) : ~m);
}
__device__ __forceinline__ size_t hm_dest(int m, int n) {
    int b = m >> 11, q = m & (SEQ-1);
    int h = n >> 6,  d = n & (HD-1);
    return ((size_t)b << 21) + ((size_t)h << 17) + ((size_t)q << 6) + d;
}
__device__ __forceinline__ uint32_t smem_to_u32(const void* p) {
    uint32_t a;
    asm("{ .reg .u64 tmp; cvta.to.shared.u64 tmp, %1; cvt.u32.u64 %0, tmp; }"
        : "=r"(a) : "l"(p));
    return a;
}

// m16n8k16 bf16 MMA, fp32 accumulate (arch-neutral PTX -> HMMA)
__device__ __forceinline__ void mma16816(float c[4], const uint32_t a[4],
                                         const uint32_t b[2]) {
    asm volatile(
        "mma.sync.aligned.m16n8k16.row.col.f32.bf16.bf16.f32 "
        "{%0,%1,%2,%3}, {%4,%5,%6,%7}, {%8,%9}, {%0,%1,%2,%3};"
        : "+f"(c[0]), "+f"(c[1]), "+f"(c[2]), "+f"(c[3])
        : "r"(a[0]), "r"(a[1]), "r"(a[2]), "r"(a[3]), "r"(b[0]), "r"(b[1]));
}
// ldmatrix x4 (arch-neutral, sm_75+)
__device__ __forceinline__ void ldm_x4(uint32_t r[4], uint32_t addr) {
    asm volatile("ldmatrix.sync.aligned.m8n8.x4.shared.b16 {%0,%1,%2,%3}, [%4];"
        : "=r"(r[0]), "=r"(r[1]), "=r"(r[2]), "=r"(r[3]) : "r"(addr));
}
// 16B async copy global -> shared (L2-cached)
__device__ __forceinline__ void cp16(uint32_t smem_addr, const void* gptr) {
    asm volatile("cp.async.cg.shared.global [%0], [%1], 16;"
                 :: "r"(smem_addr), "l"(gptr) : "memory");
}

// ---------------------------------------------------------------------------
// merged bf16 split kernel: x, Wv, Wo in one launch
// ---------------------------------------------------------------------------
__global__ void split_all_kernel(
    const float* __restrict__ x,  __nv_bfloat16* __restrict__ xh,  __nv_bfloat16* __restrict__ xl,
    const float* __restrict__ Wv, __nv_bfloat16* __restrict__ Wvh, __nv_bfloat16* __restrict__ Wvl,
    const float* __restrict__ Wo, __nv_bfloat16* __restrict__ Woh, __nv_bfloat16* __restrict__ Wol)
{
    int i = blockIdx.x * blockDim.x + threadIdx.x;
    const float* src; __nv_bfloat16 *ph, *pl; int idx;
    if (i < NELM)                { src = x;  ph = xh;  pl = xl;  idx = i; }
    else if (i < NELM + DM*DM)   { src = Wv; ph = Wvh; pl = Wvl; idx = i - NELM; }
    else                         { src = Wo; ph = Woh; pl = Wol; idx = i - NELM - DM*DM; }
    float v = src[idx];
    __nv_bfloat16 h = __float2bfloat16(v);
    ph[idx] = h;
    pl[idx] = __float2bfloat16(v - __bfloat162float(h));
}

// ---------------------------------------------------------------------------
// Tensor GEMM via mma.sync + ldmatrix, cp.async-pipelined chunk loads.
// Math (pair order, fragment mapping, accumulation sequence) byte-identical
// to the measured round-11/15/16 versions -> bitwise-same outputs.
// Block tile 128x128, 8 warps (4m x 2n), warp tile 32x64.
// CHUNKU = u32 per row per chunk (32 -> 64 bf16, 16 -> 32 bf16).
// PITCHP = smem row pitch in u32 (36 for CHUNKU=32, 20 for CHUNKU=16; both
// give conflict-free ldmatrix row addressing).
// NSTAGE-deep cp.async pipeline (stages cycle; trailing syncthreads guards
// buffer reuse exactly as in the proven 2-stage version).
// ---------------------------------------------------------------------------
template<int NSPLIT, int NSTAGE, int CHUNKU, int PITCHP>
__global__ __launch_bounds__(256) void gemm_mma(
    const __nv_bfloat16* __restrict__ A0, const __nv_bfloat16* __restrict__ A1,
    const __nv_bfloat16* __restrict__ A2, int lda, size_t sA,
    const __nv_bfloat16* __restrict__ B0, const __nv_bfloat16* __restrict__ B1,
    const __nv_bfloat16* __restrict__ B2, int ldb, size_t sB,
    const float* __restrict__ bias,
    float* __restrict__ Cout, int ldc, size_t sC,
    int Kdim, float alpha, int headmajor)
{
    extern __shared__ uint32_t sm[];
    const uint32_t sbase = smem_to_u32(sm);
    const int PLANE_U = 128*PITCHP;
    const int STAGE_U = NSPLIT*2*PLANE_U;
    const int KSTEPS  = CHUNKU/8;        // k16 steps per chunk
    const int GRAN    = CHUNKU/8;        // 16B granules per thread per plane
    const int GCW     = CHUNKU/4;        // granule columns per row

    const int t    = threadIdx.x;
    const int wid  = t >> 5, lane = t & 31;
    const int wm   = wid & 3, wn = wid >> 2;
    const int g    = lane >> 2;
    const int tq   = lane & 3;
    const int m0   = blockIdx.y * 128;
    const int n0   = blockIdx.x * 128;

    const uint32_t* Ap[3] = { (const uint32_t*)(A0 + blockIdx.z*sA),
                              (const uint32_t*)(A1 ? A1 + blockIdx.z*sA : A0),
                              (const uint32_t*)(A2 ? A2 + blockIdx.z*sA : A0) };
    const uint32_t* Bp[3] = { (const uint32_t*)(B0 + blockIdx.z*sB),
                              (const uint32_t*)(B1 ? B1 + blockIdx.z*sB : B0),
                              (const uint32_t*)(B2 ? B2 + blockIdx.z*sB : B0) };
    Cout += blockIdx.z * sC;

    float c[2][8][4];
    #pragma unroll
    for (int i = 0; i < 2; i++)
        #pragma unroll
        for (int j = 0; j < 8; j++)
            #pragma unroll
            for (int k = 0; k < 4; k++) c[i][j][k] = 0.f;

    const int lda2 = lda >> 1, ldb2 = ldb >> 1;
    const int nchunk = Kdim / (CHUNKU*2);
    const int npairs = (NSPLIT == 2) ? 3 : 6;
    const int pa[6] = {0,0,1,1,0,2};
    const int pb[6] = {0,1,0,1,2,0};

    auto load_chunk = [&](int cc, int s) {
        int kb = cc * CHUNKU;
        int stU = s * STAGE_U;
        #pragma unroll
        for (int p = 0; p < NSPLIT; p++) {
            const uint32_t* srcA = Ap[p];
            const uint32_t* srcB = Bp[p];
            #pragma unroll
            for (int i = 0; i < GRAN; i++) {
                int gid  = t + (i << 8);
                int row  = gid / GCW;
                int gcol = (gid % GCW) << 2;
                cp16(sbase + 4*(stU + p*PLANE_U + row*PITCHP + gcol),
                     srcA + (size_t)(m0 + row)*lda2 + kb + gcol);
                cp16(sbase + 4*(stU + (NSPLIT + p)*PLANE_U + row*PITCHP + gcol),
                     srcB + (size_t)(n0 + row)*ldb2 + kb + gcol);
            }
        }
        asm volatile("cp.async.commit_group;" ::: "memory");
    };

    // ldmatrix lane-address components
    const int a_row_in = (lane & 15);
    const int a_cadd   = (lane >> 4) << 2;
    const int b_row_in = (lane & 7) + ((lane >> 4) << 3);
    const int b_cadd   = ((lane >> 3) & 1) << 2;

    // preload
    load_chunk(0, 0);
    if (NSTAGE >= 3 && nchunk > 1) load_chunk(1, 1);

    for (int cc = 0; cc < nchunk; cc++) {
        int nx = cc + NSTAGE - 1;
        if (nx < nchunk) load_chunk(nx, nx % NSTAGE);
        int rem = nchunk - 1 - cc;
        if (NSTAGE >= 3 && rem >= 2)
            asm volatile("cp.async.wait_group 2;" ::: "memory");
        else if (rem >= 1)
            asm volatile("cp.async.wait_group 1;" ::: "memory");
        else
            asm volatile("cp.async.wait_group 0;" ::: "memory");
        __syncthreads();

        int stU = (cc % NSTAGE) * STAGE_U;
        #pragma unroll
        for (int ks = 0; ks < KSTEPS; ks++) {
            #pragma unroll 6
            for (int pp = 0; pp < npairs; pp++) {
                uint32_t abase = sbase + 4*(stU + pa[pp]*PLANE_U);
                uint32_t bbase = sbase + 4*(stU + (NSPLIT + pb[pp])*PLANE_U);
                uint32_t af[2][4];
                #pragma unroll
                for (int mt = 0; mt < 2; mt++) {
                    int row = wm*32 + mt*16 + a_row_in;
                    ldm_x4(af[mt], abase + 4*(row*PITCHP + ks*8 + a_cadd));
                }
                uint32_t bf[8][2];
                #pragma unroll
                for (int nt2 = 0; nt2 < 4; nt2++) {
                    int row = wn*64 + nt2*16 + b_row_in;
                    uint32_t r4[4];
                    ldm_x4(r4, bbase + 4*(row*PITCHP + ks*8 + b_cadd));
                    bf[nt2*2+0][0] = r4[0]; bf[nt2*2+0][1] = r4[1];
                    bf[nt2*2+1][0] = r4[2]; bf[nt2*2+1][1] = r4[3];
                }
                #pragma unroll
                for (int mt = 0; mt < 2; mt++)
                    #pragma unroll
                    for (int nt = 0; nt < 8; nt++)
                        mma16816(c[mt][nt], af[mt], bf[nt]);
            }
        }
        __syncthreads();
    }

    // epilogue
    #pragma unroll
    for (int mt = 0; mt < 2; mt++) {
        #pragma unroll
        for (int half = 0; half < 2; half++) {
            int m = m0 + wm*32 + mt*16 + g + half*8;
            #pragma unroll
            for (int nt = 0; nt < 8; nt++) {
                int n = n0 + wn*64 + nt*8 + tq*2;
                float2 r;
                r.x = alpha*c[mt][nt][half*2+0] + (bias ? bias[n]   : 0.f);
                r.y = alpha*c[mt][nt][half*2+1] + (bias ? bias[n+1] : 0.f);
                float* dst = headmajor ? (Cout + hm_dest(m, n))
                                       : (Cout + (size_t)m*ldc + n);
                *(float2*)dst = r;
            }
        }
    }
}

// ---------------------------------------------------------------------------
// High-accuracy two-level (Kahan) GEMM — Q AND K projections in ONE launch
// (blockIdx.z: 0=Q, 1=K). At the FFMA roofline (fma issue-saturated); the
// per-thread numeric sequence is identical to rounds 6-16. Do not touch.
// ---------------------------------------------------------------------------
__global__ __launch_bounds__(256) void gemm_2lvl_qk(
    const float* __restrict__ A, int lda,
    const float* __restrict__ Wq, const float* __restrict__ Wk,
    const float* __restrict__ bq, const float* __restrict__ bk,
    __nv_bfloat16* __restrict__ Qhp, __nv_bfloat16* __restrict__ Qmp,
    __nv_bfloat16* __restrict__ Qlp,
    __nv_bfloat16* __restrict__ Khp, __nv_bfloat16* __restrict__ Kmp,
    __nv_bfloat16* __restrict__ Klp, int Kdim)
{
    const float* W    = blockIdx.z ? Wk : Wq;
    const float* bias = blockIdx.z ? bk : bq;
    __nv_bfloat16* Phi  = blockIdx.z ? Khp : Qhp;
    __nv_bfloat16* Pmid = blockIdx.z ? Kmp : Qmp;
    __nv_bfloat16* Plo  = blockIdx.z ? Klp : Qlp;

    __shared__ float As[2][16][128];
    __shared__ float Ws[2][16][64];
    int t  = threadIdx.x;
    int m0 = blockIdx.y * 128;
    int n0 = blockIdx.x * 64;
    int tm = t >> 4, tn = t & 15;
    int lr = t >> 2;
    int lc = (t & 3) << 2;

    float acc[8][4], cmp[8][4];
    #pragma unroll
    for (int i = 0; i < 8; i++)
        #pragma unroll
        for (int j = 0; j < 4; j++) { acc[i][j] = 0.f; cmp[i][j] = 0.f; }

    float4 a0, a1, w0;
    a0 = *(const float4*)(A + (size_t)(m0+lr   )*lda + lc);
    a1 = *(const float4*)(A + (size_t)(m0+lr+64)*lda + lc);
    w0 = *(const float4*)(W + (size_t)(n0+lr   )*lda + lc);
    As[0][lc+0][lr]    = a0.x; As[0][lc+1][lr]    = a0.y; As[0][lc+2][lr]    = a0.z; As[0][lc+3][lr]    = a0.w;
    As[0][lc+0][lr+64] = a1.x; As[0][lc+1][lr+64] = a1.y; As[0][lc+2][lr+64] = a1.z; As[0][lc+3][lr+64] = a1.w;
    Ws[0][lc+0][lr]    = w0.x; Ws[0][lc+1][lr]    = w0.y; Ws[0][lc+2][lr]    = w0.z; Ws[0][lc+3][lr]    = w0.w;
    __syncthreads();

    int nt = Kdim >> 4;
    for (int it = 0; it < nt; it++) {
        int cur = it & 1;
        if (it + 1 < nt) {
            int k0 = (it + 1) << 4;
            a0 = *(const float4*)(A + (size_t)(m0+lr   )*lda + k0 + lc);
            a1 = *(const float4*)(A + (size_t)(m0+lr+64)*lda + k0 + lc);
            w0 = *(const float4*)(W + (size_t)(n0+lr   )*lda + k0 + lc);
        }
        float tmp[8][4];
        #pragma unroll
        for (int i = 0; i < 8; i++)
            #pragma unroll
            for (int j = 0; j < 4; j++) tmp[i][j] = 0.f;
        #pragma unroll
        for (int kk = 0; kk < 16; kk++) {
            float a[8], bb[4];
            *(float4*)(a)    = *(const float4*)&As[cur][kk][tm*8];
            *(float4*)(a+4)  = *(const float4*)&As[cur][kk][tm*8+4];
            *(float4*)(bb)   = *(const float4*)&Ws[cur][kk][tn*4];
            #pragma unroll
            for (int i = 0; i < 8; i++)
                #pragma unroll
                for (int j = 0; j < 4; j++)
                    tmp[i][j] = fmaf(a[i], bb[j], tmp[i][j]);
        }
        #pragma unroll
        for (int i = 0; i < 8; i++)
            #pragma unroll
            for (int j = 0; j < 4; j++) {
                float y = tmp[i][j] - cmp[i][j];
                float s = acc[i][j] + y;
                cmp[i][j] = (s - acc[i][j]) - y;
                acc[i][j] = s;
            }
        if (it + 1 < nt) {
            int nx = (it + 1) & 1;
            As[nx][lc+0][lr]    = a0.x; As[nx][lc+1][lr]    = a0.y; As[nx][lc+2][lr]    = a0.z; As[nx][lc+3][lr]    = a0.w;
            As[nx][lc+0][lr+64] = a1.x; As[nx][lc+1][lr+64] = a1.y; As[nx][lc+2][lr+64] = a1.z; As[nx][lc+3][lr+64] = a1.w;
            Ws[nx][lc+0][lr]    = w0.x; Ws[nx][lc+1][lr]    = w0.y; Ws[nx][lc+2][lr]    = w0.z; Ws[nx][lc+3][lr]    = w0.w;
            __syncthreads();
        }
    }
    #pragma unroll
    for (int i = 0; i < 8; i++) {
        int m = m0 + tm*8 + i;
        int n = n0 + tn*4;
        size_t di = hm_dest(m, n);
        #pragma unroll
        for (int j = 0; j < 4; j++) {
            float v = acc[i][j] + bias[n+j];
            __nv_bfloat16 h = __float2bfloat16(v);
            float r1 = v - __bfloat162float(h);
            __nv_bfloat16 md = __float2bfloat16(r1);
            float r2 = r1 - __bfloat162float(md);
            Phi[di+j]  = h;
            Pmid[di+j] = md;
            Plo[di+j]  = __float2bfloat16(r2);
        }
    }
}

// ---------------------------------------------------------------------------
// Select kernel (unchanged passing logic).
// ---------------------------------------------------------------------------
__global__ __launch_bounds__(256) void select_kernel(
    const float* __restrict__ S, const float* __restrict__ V,
    __nv_bfloat16* __restrict__ Chi, __nv_bfloat16* __restrict__ Clo)
{
    int t    = threadIdx.x;
    int qq   = t >> 5;
    int lane = t & 31;
    int bh   = blockIdx.y;
    int b    = bh >> 4, h = bh & 15;
    int q    = blockIdx.x * QB + qq;

    const float4* Srow = (const float4*)(S + ((size_t)bh*SEQ + q)*SEQ);

    unsigned u[64];
    unsigned umax = 0u;
    unsigned c0=0,c1=0,c2=0,c3=0,c4=0,c5=0;
    #pragma unroll
    for (int i = 0; i < 16; i++) {
        float4 v = Srow[i*32 + lane];
        unsigned uu[4] = { f2u(v.x), f2u(v.y), f2u(v.z), f2u(v.w) };
        #pragma unroll
        for (int s = 0; s < 4; s++) {
            unsigned w = uu[s];
            u[4*i+s] = w;
            if (w > c5) {
                c5 = w;
                if (c5 > c4) { unsigned x=c4; c4=c5; c5=x; }
                if (c4 > c3) { unsigned x=c3; c3=c4; c4=x; }
                if (c3 > c2) { unsigned x=c2; c2=c3; c3=x; }
                if (c2 > c1) { unsigned x=c1; c1=c2; c2=x; }
                if (c1 > c0) { unsigned x=c0; c0=c1; c1=x; }
            }
        }
    }
    umax = c0;
    #pragma unroll
    for (int o = 16; o; o >>= 1)
        umax = max(umax, __shfl_xor_sync(0xffffffffu, umax, o));

    unsigned lo = 0u, hi = umax;
    while (lo < hi) {
        unsigned d   = hi - lo;
        unsigned mid = lo + (d >> 1) + (d & 1u);
        int c = (c0>=mid) + (c1>=mid) + (c2>=mid) + (c3>=mid) + (c4>=mid) + (c5>=mid);
        #pragma unroll
        for (int o = 16; o; o >>= 1) c += __shfl_xor_sync(0xffffffffu, c, o);
        if (c >= UTOP) lo = mid; else hi = mid - 1;
    }
    unsigned uth = lo;
    {
        int pack = 0;
        #pragma unroll
        for (int j = 0; j < 64; j++) {
            pack += (u[j] >= uth) ? 1 : 0;
            pack += (u[j] >  uth) ? (1 << 16) : 0;
        }
        #pragma unroll
        for (int o = 16; o; o >>= 1) pack += __shfl_xor_sync(0xffffffffu, pack, o);
        int cge = pack & 0xFFFF, cgt = pack >> 16;
        if (!(cge >= UTOP && cgt < UTOP)) {
            lo = 0u; hi = umax;
            while (lo < hi) {
                unsigned d   = hi - lo;
                unsigned mid = lo + (d >> 1) + (d & 1u);
                int c = 0;
                #pragma unroll
                for (int j = 0; j < 64; j++) c += (u[j] >= mid) ? 1 : 0;
                #pragma unroll
                for (int o = 16; o; o >>= 1) c += __shfl_xor_sync(0xffffffffu, c, o);
                if (c >= UTOP) lo = mid; else hi = mid - 1;
            }
            uth = lo;
        }
    }
    const float mymax = u2f(umax);

    const float* Vb = V + ((size_t)bh*SEQ)*HD;
    float sum = 0.f, acc0 = 0.f, acc1 = 0.f;
    #pragma unroll
    for (int j = 0; j < 64; j++) {
        bool keep = (u[j] >= uth);
        float p = keep ? __expf(u2f(u[j]) - mymax) : 0.f;
        sum += p;
        unsigned msk = __ballot_sync(0xffffffffu, keep);
        int kb = ((j >> 2) << 7) + (j & 3);
        while (msk) {
            int src = __ffs(msk) - 1; msk &= msk - 1;
            float pb = __shfl_sync(0xffffffffu, p, src);
            const float* vr = Vb + (size_t)(kb + (src << 2))*HD;
            acc0 = fmaf(pb, vr[lane],      acc0);
            acc1 = fmaf(pb, vr[lane + 32], acc1);
        }
    }
    #pragma unroll
    for (int o = 16; o; o >>= 1) sum += __shfl_xor_sync(0xffffffffu, sum, o);
    float inv = 1.f / sum;

    size_t o0 = ((size_t)(b*SEQ + q))*DM + h*HD;
    float v0 = acc0 * inv, v1 = acc1 * inv;
    __nv_bfloat16 h0 = __float2bfloat16(v0);
    __nv_bfloat16 h1 = __float2bfloat16(v1);
    Chi[o0 + lane]      = h0;
    Clo[o0 + lane]      = __float2bfloat16(v0 - __bfloat162float(h0));
    Chi[o0 + lane + 32] = h1;
    Clo[o0 + lane + 32] = __float2bfloat16(v1 - __bfloat162float(h1));
}

// ---------------------------------------------------------------------------
extern "C" void kernel_launch(void* const* d_in, const int* in_sizes, int n_in,
                              void* d_out, int out_size)
{
    const float* x  = (const float*)d_in[0];
    const float* Wq = (const float*)d_in[1];
    const float* bq = (const float*)d_in[2];
    const float* Wk = (const float*)d_in[3];
    const float* bk = (const float*)d_in[4];
    const float* Wv = (const float*)d_in[5];
    const float* bv = (const float*)d_in[6];
    const float* Wo = (const float*)d_in[7];
    const float* bo = (const float*)d_in[8];
    float* out = (float*)d_out;

    float *Sp, *Vp;
    __nv_bfloat16 *xh,*xl,*Wvh,*Wvl,*Woh,*Wol,*Qh,*Qm,*Ql,*Kh,*Km,*Kl,*Ch,*Cl;
    cudaGetSymbolAddress((void**)&Sp,  g_S);
    cudaGetSymbolAddress((void**)&Vp,  g_V);
    cudaGetSymbolAddress((void**)&xh,  g_xh);  cudaGetSymbolAddress((void**)&xl,  g_xl);
    cudaGetSymbolAddress((void**)&Wvh, g_Wvh); cudaGetSymbolAddress((void**)&Wvl, g_Wvl);
    cudaGetSymbolAddress((void**)&Woh, g_Woh); cudaGetSymbolAddress((void**)&Wol, g_Wol);
    cudaGetSymbolAddress((void**)&Qh,  g_Qh);  cudaGetSymbolAddress((void**)&Qm,  g_Qm);
    cudaGetSymbolAddress((void**)&Ql,  g_Ql);
    cudaGetSymbolAddress((void**)&Kh,  g_Kh);  cudaGetSymbolAddress((void**)&Km,  g_Km);
    cudaGetSymbolAddress((void**)&Kl,  g_Kl);
    cudaGetSymbolAddress((void**)&Ch,  g_Ch);  cudaGetSymbolAddress((void**)&Cl,  g_Cl);

    // V/O: NSPLIT=2, NSTAGE=3, CHUNKU=32(64 bf16), PITCH=36
    const int SMVO = 3 * (2*2*128*36*4);      // 221184 B
    // score: NSPLIT=3, NSTAGE=2, CHUNKU=16(32 bf16), PITCH=20
    const int SMSC = 2 * (3*2*128*20*4);      // 122880 B
    cudaFuncSetAttribute((const void*)gemm_mma<2,3,32,36>,
                         cudaFuncAttributeMaxDynamicSharedMemorySize, SMVO);
    cudaFuncSetAttribute((const void*)gemm_mma<3,2,16,20>,
                         cudaFuncAttributeMaxDynamicSharedMemorySize, SMSC);

    const int M = BATCH * SEQ;   // 4096

    // input splits (merged launch)
    split_all_kernel<<<(NELM + 2*DM*DM)/256, 256>>>(x, xh, xl, Wv, Wvh, Wvl,
                                                    Wo, Woh, Wol);

    // Q + K projections in one launch (Kahan FFMA, bf16x3 planes out)
    gemm_2lvl_qk<<<dim3(DM/64, M/128, 2), 256>>>(x, DM, Wq, Wk, bq, bk,
                                                 Qh, Qm, Ql, Kh, Km, Kl, DM);

    // V projection (bf16x2, 3-stage cp.async, head-major fp32 out)
    gemm_mma<2,3,32,36><<<dim3(DM/128, M/128, 1), 256, SMVO>>>(
        xh, xl, (const __nv_bfloat16*)0, DM, 0,
        Wvh, Wvl, (const __nv_bfloat16*)0, DM, 0,
        bv, Vp, 0, 0, DM, 1.f, 1);

    // Scores (bf16x3, 2-chunk 2-stage pipeline)
    gemm_mma<3,2,16,20><<<dim3(SEQ/128, SEQ/128, BATCH*NH), 256, SMSC>>>(
        Qh, Qm, Ql, HD, (size_t)SEQ*HD,
        Kh, Km, Kl, HD, (size_t)SEQ*HD,
        (const float*)0, Sp, SEQ, (size_t)SEQ*SEQ, HD, 0.125f, 0);

    // Top-38 select + softmax + sparse AV (context emitted as bf16 hi/lo)
    select_kernel<<<dim3(SEQ/QB, BATCH*NH), 256>>>(Sp, Vp, Ch, Cl);

    // Output projection (bf16x2, 3-stage cp.async)
    gemm_mma<2,3,32,36><<<dim3(DM/128, M/128, 1), 256, SMVO>>>(
        Ch, Cl, (const __nv_bfloat16*)0, DM, 0,
        Woh, Wol, (const __nv_bfloat16*)0, DM, 0,
        bo, out, DM, 0, DM, 1.f, 0);
}